// round 1
// baseline (speedup 1.0000x reference)
#include <cuda_runtime.h>
#include <cstdint>

// Problem constants (fixed by the dataset)
constexpr int    kN  = 100000;           // nodes
constexpr int    kF  = 64;               // feature dim
constexpr size_t kHS = (size_t)kN * kF;  // one [N,64] buffer, in floats

// Scratch layout inside one big device buffer:
//   H0..H5   : 6 x [N,64]  raw aggregation outputs (pre output-scale)
//   T0..T3   : 4 x [N,64]  inner second-order temporaries
//   deg_out, deg_in                 : [N] each
//   dT0..dT3 (second-order degrees) : [N] each
//   sc0..sc5 (inv-sqrt scales)      : [N] each  (order: iso, isi, sAAt, sAtA, sAAo, sAAi)
constexpr size_t kDegOut = 10 * kHS;
constexpr size_t kDegIn  = kDegOut + kN;
constexpr size_t kDT     = kDegIn + kN;
constexpr size_t kSC     = kDT + 4 * (size_t)kN;
constexpr size_t kTotal  = kSC + 6 * (size_t)kN;

__device__ float g_buf[kTotal];

// -------------------- helpers --------------------

__device__ __forceinline__ void red2(float* p, float a, float b) {
    // fire-and-forget vector reduction into global memory (sm_90+)
    asm volatile("red.global.add.v2.f32 [%0], {%1, %2};"
                 :: "l"(p), "f"(a), "f"(b) : "memory");
}

__device__ __forceinline__ float invs(float d) {
    return d > 0.f ? rsqrtf(d) : 0.f;
}

// -------------------- kernels --------------------

__global__ void k_zero() {
    const size_t n4 = kTotal / 4;
    float4* p = reinterpret_cast<float4*>(g_buf);
    for (size_t i = (size_t)blockIdx.x * blockDim.x + threadIdx.x; i < n4;
         i += (size_t)gridDim.x * blockDim.x)
        p[i] = make_float4(0.f, 0.f, 0.f, 0.f);
}

__global__ void k_deg(const int* __restrict__ ei, int E) {
    int e = blockIdx.x * blockDim.x + threadIdx.x;
    if (e >= E) return;
    int r = ei[e];
    int c = ei[E + e];
    atomicAdd(&g_buf[kDegOut + r], 1.f);
    atomicAdd(&g_buf[kDegIn + c], 1.f);
}

__global__ void k_deg2(const int* __restrict__ ei, int E) {
    int e = blockIdx.x * blockDim.x + threadIdx.x;
    if (e >= E) return;
    int r = ei[e];
    int c = ei[E + e];
    float dout_r = g_buf[kDegOut + r];
    float dout_c = g_buf[kDegOut + c];
    float din_r  = g_buf[kDegIn + r];
    float din_c  = g_buf[kDegIn + c];
    atomicAdd(&g_buf[kDT + 0 * (size_t)kN + r], din_c);   // Av(d_in)
    atomicAdd(&g_buf[kDT + 1 * (size_t)kN + c], dout_r);  // Atv(d_out)
    atomicAdd(&g_buf[kDT + 2 * (size_t)kN + r], dout_c);  // Av(d_out)
    atomicAdd(&g_buf[kDT + 3 * (size_t)kN + c], din_r);   // Atv(d_in)
}

__global__ void k_scales(int n) {
    int i = blockIdx.x * blockDim.x + threadIdx.x;
    if (i >= n) return;
    g_buf[kSC + 0 * (size_t)kN + i] = invs(g_buf[kDegOut + i]);              // iso
    g_buf[kSC + 1 * (size_t)kN + i] = invs(g_buf[kDegIn + i]);               // isi
    g_buf[kSC + 2 * (size_t)kN + i] = invs(g_buf[kDT + 0 * (size_t)kN + i]); // sAAt
    g_buf[kSC + 3 * (size_t)kN + i] = invs(g_buf[kDT + 1 * (size_t)kN + i]); // sAtA
    g_buf[kSC + 4 * (size_t)kN + i] = invs(g_buf[kDT + 2 * (size_t)kN + i]); // sAAo
    g_buf[kSC + 5 * (size_t)kN + i] = invs(g_buf[kDT + 3 * (size_t)kN + i]); // sAAi
}

// Pass A: one edge pass performing all 6 input-scaled first-hop SpMMs.
//   H0[r] += isi[c] *x[c]    (A_x raw)
//   H1[c] += iso[r] *x[r]    (At_x raw)
//   T0[c] += sAAt[r]*x[r]    (chain AAt inner: Atv(sAAt*x))
//   T1[r] += sAtA[c]*x[c]    (chain AtA inner: Av(sAtA*x))
//   T2[r] += sAAi[c]*x[c]    (chain AA  inner: Av(sAAi*x))
//   T3[c] += sAAo[r]*x[r]    (chain AtAt inner: Atv(sAAo*x))
__global__ void __launch_bounds__(256) k_pass_a(const float* __restrict__ x,
                                                const int* __restrict__ ei, int E) {
    int gwarp = (blockIdx.x * 256 + threadIdx.x) >> 5;
    int lane  = threadIdx.x & 31;
    long base = (long)gwarp * 32;
    if (base >= E) return;

    int idx = (int)base + lane;
    int r0 = 0, c0 = 0;
    if (idx < E) { r0 = ei[idx]; c0 = ei[E + idx]; }
    int cnt = E - (int)base;
    if (cnt > 32) cnt = 32;

    const float* iso  = g_buf + kSC + 0 * (size_t)kN;
    const float* isi  = g_buf + kSC + 1 * (size_t)kN;
    const float* sAAt = g_buf + kSC + 2 * (size_t)kN;
    const float* sAtA = g_buf + kSC + 3 * (size_t)kN;
    const float* sAAo = g_buf + kSC + 4 * (size_t)kN;
    const float* sAAi = g_buf + kSC + 5 * (size_t)kN;

    float* H0 = g_buf + 0 * kHS;
    float* H1 = g_buf + 1 * kHS;
    float* T0 = g_buf + 6 * kHS;
    float* T1 = g_buf + 7 * kHS;
    float* T2 = g_buf + 8 * kHS;
    float* T3 = g_buf + 9 * kHS;

    for (int j = 0; j < cnt; j++) {
        int r = __shfl_sync(0xffffffffu, r0, j);
        int c = __shfl_sync(0xffffffffu, c0, j);
        size_t ro = (size_t)r * kF + 2 * lane;
        size_t co = (size_t)c * kF + 2 * lane;
        float2 xc = *(const float2*)(x + co);
        float2 xr = *(const float2*)(x + ro);
        float s_isi  = __ldg(isi + c);
        float s_sAtA = __ldg(sAtA + c);
        float s_sAAi = __ldg(sAAi + c);
        float s_iso  = __ldg(iso + r);
        float s_sAAt = __ldg(sAAt + r);
        float s_sAAo = __ldg(sAAo + r);

        red2(H0 + ro, xc.x * s_isi,  xc.y * s_isi);
        red2(T1 + ro, xc.x * s_sAtA, xc.y * s_sAtA);
        red2(T2 + ro, xc.x * s_sAAi, xc.y * s_sAAi);
        red2(H1 + co, xr.x * s_iso,  xr.y * s_iso);
        red2(T0 + co, xr.x * s_sAAt, xr.y * s_sAAt);
        red2(T3 + co, xr.x * s_sAAo, xr.y * s_sAAo);
    }
}

// Pass B: one edge pass performing the 4 second-hop SpMMs.
//   H2[r] += T0[c]   (Av)
//   H3[c] += T1[r]   (Atv)
//   H4[r] += T2[c]   (Av)
//   H5[c] += T3[r]   (Atv)
__global__ void __launch_bounds__(256) k_pass_b(const int* __restrict__ ei, int E) {
    int gwarp = (blockIdx.x * 256 + threadIdx.x) >> 5;
    int lane  = threadIdx.x & 31;
    long base = (long)gwarp * 32;
    if (base >= E) return;

    int idx = (int)base + lane;
    int r0 = 0, c0 = 0;
    if (idx < E) { r0 = ei[idx]; c0 = ei[E + idx]; }
    int cnt = E - (int)base;
    if (cnt > 32) cnt = 32;

    float* H2 = g_buf + 2 * kHS;
    float* H3 = g_buf + 3 * kHS;
    float* H4 = g_buf + 4 * kHS;
    float* H5 = g_buf + 5 * kHS;
    const float* T0 = g_buf + 6 * kHS;
    const float* T1 = g_buf + 7 * kHS;
    const float* T2 = g_buf + 8 * kHS;
    const float* T3 = g_buf + 9 * kHS;

    for (int j = 0; j < cnt; j++) {
        int r = __shfl_sync(0xffffffffu, r0, j);
        int c = __shfl_sync(0xffffffffu, c0, j);
        size_t ro = (size_t)r * kF + 2 * lane;
        size_t co = (size_t)c * kF + 2 * lane;
        float2 t0 = *(const float2*)(T0 + co);
        float2 t1 = *(const float2*)(T1 + ro);
        float2 t2 = *(const float2*)(T2 + co);
        float2 t3 = *(const float2*)(T3 + ro);
        red2(H2 + ro, t0.x, t0.y);
        red2(H3 + co, t1.x, t1.y);
        red2(H4 + ro, t2.x, t2.y);
        red2(H5 + co, t3.x, t3.y);
    }
}

// Fused epilogue GEMM:
//   out[n,:] = sum_i 0.75 * sc_i[n] * (H_i[n,:] @ W_i)  +  0.75 * sum_i b_i
// (ALPHA=BETA=GAMA=0.5 -> every coefficient (1+a)*a = (1+a)*(1-a) = 0.75)
__global__ void __launch_bounds__(128) k_gemm(
    const float* __restrict__ Wsd, const float* __restrict__ bsd,
    const float* __restrict__ Wds, const float* __restrict__ bds,
    const float* __restrict__ W0,  const float* __restrict__ b0,
    const float* __restrict__ W1,  const float* __restrict__ b1,
    const float* __restrict__ W2,  const float* __restrict__ b2,
    const float* __restrict__ W3,  const float* __restrict__ b3,
    float* __restrict__ out, int n) {
    __shared__ float Wsh[64 * 64];
    __shared__ float btot[64];

    int tid  = threadIdx.x;
    int node = blockIdx.x * 128 + tid;

    if (tid < 64)
        btot[tid] = 0.75f * (bsd[tid] + bds[tid] + b0[tid] + b1[tid] + b2[tid] + b3[tid]);

    float acc[64];
#pragma unroll
    for (int f = 0; f < 64; f++) acc[f] = 0.f;

    const float* Ws[6] = {Wsd, Wds, W0, W1, W2, W3};

#pragma unroll 1
    for (int i = 0; i < 6; i++) {
        __syncthreads();
        {
            const float4* src = (const float4*)Ws[i];
            float4* dst = (float4*)Wsh;
#pragma unroll
            for (int j = 0; j < 8; j++) dst[tid + 128 * j] = src[tid + 128 * j];
        }
        __syncthreads();

        if (node < n) {
            float s = 0.75f * g_buf[kSC + (size_t)i * kN + node];
            const float* hrow = g_buf + (size_t)i * kHS + (size_t)node * kF;
#pragma unroll 1
            for (int k = 0; k < 64; k += 4) {
                float4 h = *(const float4*)(hrow + k);
                float hv0 = h.x * s, hv1 = h.y * s, hv2 = h.z * s, hv3 = h.w * s;
#pragma unroll
                for (int f = 0; f < 64; f++) {
                    acc[f] += hv0 * Wsh[(k + 0) * 64 + f];
                    acc[f] += hv1 * Wsh[(k + 1) * 64 + f];
                    acc[f] += hv2 * Wsh[(k + 2) * 64 + f];
                    acc[f] += hv3 * Wsh[(k + 3) * 64 + f];
                }
            }
        }
    }

    if (node < n) {
#pragma unroll
        for (int f = 0; f < 64; f += 4) {
            float4 o;
            o.x = acc[f + 0] + btot[f + 0];
            o.y = acc[f + 1] + btot[f + 1];
            o.z = acc[f + 2] + btot[f + 2];
            o.w = acc[f + 3] + btot[f + 3];
            *(float4*)(out + (size_t)node * kF + f) = o;
        }
    }
}

// -------------------- launcher --------------------

extern "C" void kernel_launch(void* const* d_in, const int* in_sizes, int n_in,
                              void* d_out, int out_size) {
    const float* x  = (const float*)d_in[0];
    const int*   ei = (const int*)d_in[1];

    int nnodes = in_sizes[0] / kF;
    if (nnodes > kN) nnodes = kN;
    int E = in_sizes[1] / 2;

    const int tb = 256;

    k_zero<<<2048, tb>>>();
    k_deg<<<(E + tb - 1) / tb, tb>>>(ei, E);
    k_deg2<<<(E + tb - 1) / tb, tb>>>(ei, E);
    k_scales<<<(nnodes + tb - 1) / tb, tb>>>(nnodes);

    int warps   = (E + 31) / 32;
    int blocksA = (warps * 32 + tb - 1) / tb;
    k_pass_a<<<blocksA, tb>>>(x, ei, E);
    k_pass_b<<<blocksA, tb>>>(ei, E);

    k_gemm<<<(nnodes + 127) / 128, 128>>>(
        (const float*)d_in[2],  (const float*)d_in[3],
        (const float*)d_in[4],  (const float*)d_in[5],
        (const float*)d_in[6],  (const float*)d_in[7],
        (const float*)d_in[8],  (const float*)d_in[9],
        (const float*)d_in[10], (const float*)d_in[11],
        (const float*)d_in[12], (const float*)d_in[13],
        (float*)d_out, nnodes);
}

// round 2
// speedup vs baseline: 1.0076x; 1.0076x over previous
#include <cuda_runtime.h>
#include <cstdint>

// Problem constants (fixed by the dataset)
constexpr int    kN  = 100000;           // nodes
constexpr int    kF  = 64;               // feature dim
constexpr size_t kHS = (size_t)kN * kF;  // one [N,64] buffer, in floats

// Scratch layout inside one big device buffer:
//   H0..H5   : 6 x [N,64]  raw aggregation outputs (pre output-scale)
//   T0..T3   : 4 x [N,64]  inner second-order temporaries
//   deg_out, deg_in                 : [N] each
//   dT0..dT3 (second-order degrees) : [N] each
//   sc0..sc5 (inv-sqrt scales)      : [N] each  (order: iso, isi, sAAt, sAtA, sAAo, sAAi)
constexpr size_t kDegOut = 10 * kHS;
constexpr size_t kDegIn  = kDegOut + kN;
constexpr size_t kDT     = kDegIn + kN;
constexpr size_t kSC     = kDT + 4 * (size_t)kN;
constexpr size_t kTotal  = kSC + 6 * (size_t)kN;

__device__ float g_buf[kTotal];

// -------------------- helpers --------------------

__device__ __forceinline__ void red2(float* p, float a, float b) {
    // fire-and-forget vector reduction into global memory (sm_90+)
    asm volatile("red.global.add.v2.f32 [%0], {%1, %2};"
                 :: "l"(p), "f"(a), "f"(b) : "memory");
}

__device__ __forceinline__ float invs(float d) {
    return d > 0.f ? rsqrtf(d) : 0.f;
}

// -------------------- kernels --------------------

__global__ void k_zero() {
    const size_t n4 = kTotal / 4;
    float4* p = reinterpret_cast<float4*>(g_buf);
    for (size_t i = (size_t)blockIdx.x * blockDim.x + threadIdx.x; i < n4;
         i += (size_t)gridDim.x * blockDim.x)
        p[i] = make_float4(0.f, 0.f, 0.f, 0.f);
}

__global__ void k_deg(const int* __restrict__ ei, int E) {
    int e = blockIdx.x * blockDim.x + threadIdx.x;
    if (e >= E) return;
    int r = ei[e];
    int c = ei[E + e];
    atomicAdd(&g_buf[kDegOut + r], 1.f);
    atomicAdd(&g_buf[kDegIn + c], 1.f);
}

__global__ void k_deg2(const int* __restrict__ ei, int E) {
    int e = blockIdx.x * blockDim.x + threadIdx.x;
    if (e >= E) return;
    int r = ei[e];
    int c = ei[E + e];
    float dout_r = g_buf[kDegOut + r];
    float dout_c = g_buf[kDegOut + c];
    float din_r  = g_buf[kDegIn + r];
    float din_c  = g_buf[kDegIn + c];
    atomicAdd(&g_buf[kDT + 0 * (size_t)kN + r], din_c);   // Av(d_in)
    atomicAdd(&g_buf[kDT + 1 * (size_t)kN + c], dout_r);  // Atv(d_out)
    atomicAdd(&g_buf[kDT + 2 * (size_t)kN + r], dout_c);  // Av(d_out)
    atomicAdd(&g_buf[kDT + 3 * (size_t)kN + c], din_r);   // Atv(d_in)
}

__global__ void k_scales(int n) {
    int i = blockIdx.x * blockDim.x + threadIdx.x;
    if (i >= n) return;
    g_buf[kSC + 0 * (size_t)kN + i] = invs(g_buf[kDegOut + i]);              // iso
    g_buf[kSC + 1 * (size_t)kN + i] = invs(g_buf[kDegIn + i]);               // isi
    g_buf[kSC + 2 * (size_t)kN + i] = invs(g_buf[kDT + 0 * (size_t)kN + i]); // sAAt
    g_buf[kSC + 3 * (size_t)kN + i] = invs(g_buf[kDT + 1 * (size_t)kN + i]); // sAtA
    g_buf[kSC + 4 * (size_t)kN + i] = invs(g_buf[kDT + 2 * (size_t)kN + i]); // sAAo
    g_buf[kSC + 5 * (size_t)kN + i] = invs(g_buf[kDT + 3 * (size_t)kN + i]); // sAAi
}

// Pass A: one edge pass performing all 6 input-scaled first-hop SpMMs.
//   H0[r] += isi[c] *x[c]    (A_x raw)
//   H1[c] += iso[r] *x[r]    (At_x raw)
//   T0[c] += sAAt[r]*x[r]    (chain AAt inner: Atv(sAAt*x))
//   T1[r] += sAtA[c]*x[c]    (chain AtA inner: Av(sAtA*x))
//   T2[r] += sAAi[c]*x[c]    (chain AA  inner: Av(sAAi*x))
//   T3[c] += sAAo[r]*x[r]    (chain AtAt inner: Atv(sAAo*x))
__global__ void __launch_bounds__(256) k_pass_a(const float* __restrict__ x,
                                                const int* __restrict__ ei, int E) {
    int gwarp = (blockIdx.x * 256 + threadIdx.x) >> 5;
    int lane  = threadIdx.x & 31;
    long base = (long)gwarp * 32;
    if (base >= E) return;

    int idx = (int)base + lane;
    int r0 = 0, c0 = 0;
    if (idx < E) { r0 = ei[idx]; c0 = ei[E + idx]; }
    int cnt = E - (int)base;
    if (cnt > 32) cnt = 32;

    const float* iso  = g_buf + kSC + 0 * (size_t)kN;
    const float* isi  = g_buf + kSC + 1 * (size_t)kN;
    const float* sAAt = g_buf + kSC + 2 * (size_t)kN;
    const float* sAtA = g_buf + kSC + 3 * (size_t)kN;
    const float* sAAo = g_buf + kSC + 4 * (size_t)kN;
    const float* sAAi = g_buf + kSC + 5 * (size_t)kN;

    float* H0 = g_buf + 0 * kHS;
    float* H1 = g_buf + 1 * kHS;
    float* T0 = g_buf + 6 * kHS;
    float* T1 = g_buf + 7 * kHS;
    float* T2 = g_buf + 8 * kHS;
    float* T3 = g_buf + 9 * kHS;

    for (int j = 0; j < cnt; j++) {
        int r = __shfl_sync(0xffffffffu, r0, j);
        int c = __shfl_sync(0xffffffffu, c0, j);
        size_t ro = (size_t)r * kF + 2 * lane;
        size_t co = (size_t)c * kF + 2 * lane;
        float2 xc = *(const float2*)(x + co);
        float2 xr = *(const float2*)(x + ro);
        float s_isi  = __ldg(isi + c);
        float s_sAtA = __ldg(sAtA + c);
        float s_sAAi = __ldg(sAAi + c);
        float s_iso  = __ldg(iso + r);
        float s_sAAt = __ldg(sAAt + r);
        float s_sAAo = __ldg(sAAo + r);

        red2(H0 + ro, xc.x * s_isi,  xc.y * s_isi);
        red2(T1 + ro, xc.x * s_sAtA, xc.y * s_sAtA);
        red2(T2 + ro, xc.x * s_sAAi, xc.y * s_sAAi);
        red2(H1 + co, xr.x * s_iso,  xr.y * s_iso);
        red2(T0 + co, xr.x * s_sAAt, xr.y * s_sAAt);
        red2(T3 + co, xr.x * s_sAAo, xr.y * s_sAAo);
    }
}

// Pass B: one edge pass performing the 4 second-hop SpMMs.
//   H2[r] += T0[c]   (Av)
//   H3[c] += T1[r]   (Atv)
//   H4[r] += T2[c]   (Av)
//   H5[c] += T3[r]   (Atv)
__global__ void __launch_bounds__(256) k_pass_b(const int* __restrict__ ei, int E) {
    int gwarp = (blockIdx.x * 256 + threadIdx.x) >> 5;
    int lane  = threadIdx.x & 31;
    long base = (long)gwarp * 32;
    if (base >= E) return;

    int idx = (int)base + lane;
    int r0 = 0, c0 = 0;
    if (idx < E) { r0 = ei[idx]; c0 = ei[E + idx]; }
    int cnt = E - (int)base;
    if (cnt > 32) cnt = 32;

    float* H2 = g_buf + 2 * kHS;
    float* H3 = g_buf + 3 * kHS;
    float* H4 = g_buf + 4 * kHS;
    float* H5 = g_buf + 5 * kHS;
    const float* T0 = g_buf + 6 * kHS;
    const float* T1 = g_buf + 7 * kHS;
    const float* T2 = g_buf + 8 * kHS;
    const float* T3 = g_buf + 9 * kHS;

    for (int j = 0; j < cnt; j++) {
        int r = __shfl_sync(0xffffffffu, r0, j);
        int c = __shfl_sync(0xffffffffu, c0, j);
        size_t ro = (size_t)r * kF + 2 * lane;
        size_t co = (size_t)c * kF + 2 * lane;
        float2 t0 = *(const float2*)(T0 + co);
        float2 t1 = *(const float2*)(T1 + ro);
        float2 t2 = *(const float2*)(T2 + co);
        float2 t3 = *(const float2*)(T3 + ro);
        red2(H2 + ro, t0.x, t0.y);
        red2(H3 + co, t1.x, t1.y);
        red2(H4 + ro, t2.x, t2.y);
        red2(H5 + co, t3.x, t3.y);
    }
}

// Fused epilogue GEMM:
//   out[n,:] = sum_i 0.75 * sc_i[n] * (H_i[n,:] @ W_i)  +  0.75 * sum_i b_i
// (ALPHA=BETA=GAMA=0.5 -> every coefficient (1+a)*a = (1+a)*(1-a) = 0.75)
__global__ void __launch_bounds__(128) k_gemm(
    const float* __restrict__ Wsd, const float* __restrict__ bsd,
    const float* __restrict__ Wds, const float* __restrict__ bds,
    const float* __restrict__ W0,  const float* __restrict__ b0,
    const float* __restrict__ W1,  const float* __restrict__ b1,
    const float* __restrict__ W2,  const float* __restrict__ b2,
    const float* __restrict__ W3,  const float* __restrict__ b3,
    float* __restrict__ out, int n) {
    __shared__ float Wsh[64 * 64];
    __shared__ float btot[64];

    int tid  = threadIdx.x;
    int node = blockIdx.x * 128 + tid;

    if (tid < 64)
        btot[tid] = 0.75f * (bsd[tid] + bds[tid] + b0[tid] + b1[tid] + b2[tid] + b3[tid]);

    float acc[64];
#pragma unroll
    for (int f = 0; f < 64; f++) acc[f] = 0.f;

    const float* Ws[6] = {Wsd, Wds, W0, W1, W2, W3};

#pragma unroll 1
    for (int i = 0; i < 6; i++) {
        __syncthreads();
        {
            const float4* src = (const float4*)Ws[i];
            float4* dst = (float4*)Wsh;
#pragma unroll
            for (int j = 0; j < 8; j++) dst[tid + 128 * j] = src[tid + 128 * j];
        }
        __syncthreads();

        if (node < n) {
            float s = 0.75f * g_buf[kSC + (size_t)i * kN + node];
            const float* hrow = g_buf + (size_t)i * kHS + (size_t)node * kF;
#pragma unroll 1
            for (int k = 0; k < 64; k += 4) {
                float4 h = *(const float4*)(hrow + k);
                float hv0 = h.x * s, hv1 = h.y * s, hv2 = h.z * s, hv3 = h.w * s;
#pragma unroll
                for (int f = 0; f < 64; f++) {
                    acc[f] += hv0 * Wsh[(k + 0) * 64 + f];
                    acc[f] += hv1 * Wsh[(k + 1) * 64 + f];
                    acc[f] += hv2 * Wsh[(k + 2) * 64 + f];
                    acc[f] += hv3 * Wsh[(k + 3) * 64 + f];
                }
            }
        }
    }

    if (node < n) {
#pragma unroll
        for (int f = 0; f < 64; f += 4) {
            float4 o;
            o.x = acc[f + 0] + btot[f + 0];
            o.y = acc[f + 1] + btot[f + 1];
            o.z = acc[f + 2] + btot[f + 2];
            o.w = acc[f + 3] + btot[f + 3];
            *(float4*)(out + (size_t)node * kF + f) = o;
        }
    }
}

// -------------------- launcher --------------------

extern "C" void kernel_launch(void* const* d_in, const int* in_sizes, int n_in,
                              void* d_out, int out_size) {
    const float* x  = (const float*)d_in[0];
    const int*   ei = (const int*)d_in[1];

    int nnodes = in_sizes[0] / kF;
    if (nnodes > kN) nnodes = kN;
    int E = in_sizes[1] / 2;

    const int tb = 256;

    k_zero<<<2048, tb>>>();
    k_deg<<<(E + tb - 1) / tb, tb>>>(ei, E);
    k_deg2<<<(E + tb - 1) / tb, tb>>>(ei, E);
    k_scales<<<(nnodes + tb - 1) / tb, tb>>>(nnodes);

    int warps   = (E + 31) / 32;
    int blocksA = (warps * 32 + tb - 1) / tb;
    k_pass_a<<<blocksA, tb>>>(x, ei, E);
    k_pass_b<<<blocksA, tb>>>(ei, E);

    k_gemm<<<(nnodes + 127) / 128, 128>>>(
        (const float*)d_in[2],  (const float*)d_in[3],
        (const float*)d_in[4],  (const float*)d_in[5],
        (const float*)d_in[6],  (const float*)d_in[7],
        (const float*)d_in[8],  (const float*)d_in[9],
        (const float*)d_in[10], (const float*)d_in[11],
        (const float*)d_in[12], (const float*)d_in[13],
        (float*)d_out, nnodes);
}

// round 3
// speedup vs baseline: 1.8342x; 1.8204x over previous
#include <cuda_runtime.h>
#include <cstdint>

// Problem constants (fixed by the dataset)
constexpr int    kN  = 100000;           // nodes
constexpr int    kE  = 1600000;          // directed edges
constexpr int    kF  = 64;               // feature dim
constexpr size_t kHS = (size_t)kN * kF;  // one [N,64] buffer, in floats

// H0..H5 : raw aggregation outputs (pre output-scale), T0..T3 : inner temporaries
__device__ float  g_H[10 * kHS];
__device__ float  g_sc[6 * (size_t)kN];     // iso, isi, sAAt, sAtA, sAAo, sAAi
__device__ float4 g_p0[kN];                 // packed (isi, sAtA, sAAi) per source c  (r-side pass)
__device__ float4 g_p1[kN];                 // packed (iso, sAAt, sAAo) per source r  (c-side pass)
__device__ int    g_cnt_r[kN], g_cnt_c[kN];
__device__ int    g_rowptr[kN + 1], g_colptr[kN + 1];
__device__ int    g_cur_r[kN], g_cur_c[kN];
__device__ int    g_adjc[kE];               // dst (c) of edges grouped by src r
__device__ int    g_adjr[kE];               // src (r) of edges grouped by dst c

__device__ __forceinline__ float invs(float d) {
    return d > 0.f ? rsqrtf(d) : 0.f;
}

// -------------------- CSR build --------------------

__global__ void k_zero_cnt() {
    int i = blockIdx.x * blockDim.x + threadIdx.x;
    if (i < kN) { g_cnt_r[i] = 0; g_cnt_c[i] = 0; }
}

__global__ void k_count(const int* __restrict__ ei, int E) {
    int e = blockIdx.x * blockDim.x + threadIdx.x;
    if (e >= E) return;
    atomicAdd(&g_cnt_r[ei[e]], 1);
    atomicAdd(&g_cnt_c[ei[E + e]], 1);
}

// single-block exclusive scan of both count arrays (warp-shuffle based)
__global__ void __launch_bounds__(1024) k_scan() {
    __shared__ int wsum[32];
    __shared__ int carry;
    int lane = threadIdx.x & 31, wid = threadIdx.x >> 5;

    for (int a = 0; a < 2; a++) {
        const int* cnt = a ? g_cnt_c : g_cnt_r;
        int* ptr = a ? g_colptr : g_rowptr;
        int* cur = a ? g_cur_c : g_cur_r;
        if (threadIdx.x == 0) carry = 0;
        __syncthreads();
        for (int base = 0; base < kN; base += 1024) {
            int i = base + threadIdx.x;
            int v = (i < kN) ? cnt[i] : 0;
            int incl = v;
#pragma unroll
            for (int off = 1; off < 32; off <<= 1) {
                int t = __shfl_up_sync(0xffffffffu, incl, off);
                if (lane >= off) incl += t;
            }
            if (lane == 31) wsum[wid] = incl;
            __syncthreads();
            if (wid == 0) {
                int sv = wsum[lane];
                int si = sv;
#pragma unroll
                for (int off = 1; off < 32; off <<= 1) {
                    int t = __shfl_up_sync(0xffffffffu, si, off);
                    if (lane >= off) si += t;
                }
                wsum[lane] = si - sv;  // exclusive warp offset
            }
            __syncthreads();
            int excl = incl - v + wsum[wid] + carry;
            if (i < kN) { ptr[i] = excl; cur[i] = excl; }
            __syncthreads();
            if (wid == 31 && lane == 31) carry = excl + v;  // running total
            __syncthreads();
        }
        if (threadIdx.x == 0) ptr[kN] = carry;
        __syncthreads();
    }
}

__global__ void k_scatter(const int* __restrict__ ei, int E) {
    int e = blockIdx.x * blockDim.x + threadIdx.x;
    if (e >= E) return;
    int r = ei[e];
    int c = ei[E + e];
    g_adjc[atomicAdd(&g_cur_r[r], 1)] = c;
    g_adjr[atomicAdd(&g_cur_c[c], 1)] = r;
}

// -------------------- degrees-of-degrees + scales (fused, no atomics) --------------------

__global__ void k_deg2_scales(int n) {
    int i = blockIdx.x * blockDim.x + threadIdx.x;
    if (i >= n) return;

    float dt0 = 0.f, dt2 = 0.f;
    int s = g_rowptr[i], t = g_rowptr[i + 1];
    for (int e = s; e < t; e++) {
        int c = g_adjc[e];
        dt0 += (float)g_cnt_c[c];   // Av(d_in)
        dt2 += (float)g_cnt_r[c];   // Av(d_out)
    }
    float dt1 = 0.f, dt3 = 0.f;
    s = g_colptr[i]; t = g_colptr[i + 1];
    for (int e = s; e < t; e++) {
        int r = g_adjr[e];
        dt1 += (float)g_cnt_r[r];   // Atv(d_out)
        dt3 += (float)g_cnt_c[r];   // Atv(d_in)
    }

    float iso  = invs((float)g_cnt_r[i]);
    float isi  = invs((float)g_cnt_c[i]);
    float sAAt = invs(dt0);
    float sAtA = invs(dt1);
    float sAAo = invs(dt2);
    float sAAi = invs(dt3);

    g_sc[0 * (size_t)kN + i] = iso;
    g_sc[1 * (size_t)kN + i] = isi;
    g_sc[2 * (size_t)kN + i] = sAAt;
    g_sc[3 * (size_t)kN + i] = sAtA;
    g_sc[4 * (size_t)kN + i] = sAAo;
    g_sc[5 * (size_t)kN + i] = sAAi;
    g_p0[i] = make_float4(isi, sAtA, sAAi, 0.f);
    g_p1[i] = make_float4(iso, sAAt, sAAo, 0.f);
}

// -------------------- feature passes: warp-per-node gather-reduce --------------------

// Pass A, r-side: H0[r]=sum isi[c]x[c], T1[r]=sum sAtA[c]x[c], T2[r]=sum sAAi[c]x[c]
__global__ void __launch_bounds__(256) k_passA_r(const float* __restrict__ x) {
    int w = (blockIdx.x * 256 + threadIdx.x) >> 5;
    int lane = threadIdx.x & 31;
    if (w >= kN) return;
    int s = g_rowptr[w], t = g_rowptr[w + 1];

    float2 a0 = {0.f, 0.f}, a1 = {0.f, 0.f}, a2 = {0.f, 0.f};
    for (int b = s; b < t; b += 32) {
        int idx = b + lane;
        int c = (idx < t) ? g_adjc[idx] : 0;
        int m = t - b; if (m > 32) m = 32;
        for (int j = 0; j < m; j++) {
            int cc = __shfl_sync(0xffffffffu, c, j);
            float2 xv = *(const float2*)(x + (size_t)cc * kF + 2 * lane);
            float4 sv = g_p0[cc];
            a0.x += sv.x * xv.x; a0.y += sv.x * xv.y;
            a1.x += sv.y * xv.x; a1.y += sv.y * xv.y;
            a2.x += sv.z * xv.x; a2.y += sv.z * xv.y;
        }
    }
    size_t o = (size_t)w * kF + 2 * lane;
    *(float2*)(g_H + 0 * kHS + o) = a0;   // H0
    *(float2*)(g_H + 7 * kHS + o) = a1;   // T1
    *(float2*)(g_H + 8 * kHS + o) = a2;   // T2
}

// Pass A, c-side: H1[c]=sum iso[r]x[r], T0[c]=sum sAAt[r]x[r], T3[c]=sum sAAo[r]x[r]
__global__ void __launch_bounds__(256) k_passA_c(const float* __restrict__ x) {
    int w = (blockIdx.x * 256 + threadIdx.x) >> 5;
    int lane = threadIdx.x & 31;
    if (w >= kN) return;
    int s = g_colptr[w], t = g_colptr[w + 1];

    float2 a0 = {0.f, 0.f}, a1 = {0.f, 0.f}, a2 = {0.f, 0.f};
    for (int b = s; b < t; b += 32) {
        int idx = b + lane;
        int r = (idx < t) ? g_adjr[idx] : 0;
        int m = t - b; if (m > 32) m = 32;
        for (int j = 0; j < m; j++) {
            int rr = __shfl_sync(0xffffffffu, r, j);
            float2 xv = *(const float2*)(x + (size_t)rr * kF + 2 * lane);
            float4 sv = g_p1[rr];
            a0.x += sv.x * xv.x; a0.y += sv.x * xv.y;
            a1.x += sv.y * xv.x; a1.y += sv.y * xv.y;
            a2.x += sv.z * xv.x; a2.y += sv.z * xv.y;
        }
    }
    size_t o = (size_t)w * kF + 2 * lane;
    *(float2*)(g_H + 1 * kHS + o) = a0;   // H1
    *(float2*)(g_H + 6 * kHS + o) = a1;   // T0
    *(float2*)(g_H + 9 * kHS + o) = a2;   // T3
}

// Pass B, r-side: H2[r]=sum T0[c], H4[r]=sum T2[c]
__global__ void __launch_bounds__(256) k_passB_r() {
    int w = (blockIdx.x * 256 + threadIdx.x) >> 5;
    int lane = threadIdx.x & 31;
    if (w >= kN) return;
    int s = g_rowptr[w], t = g_rowptr[w + 1];

    const float* T0 = g_H + 6 * kHS;
    const float* T2 = g_H + 8 * kHS;
    float2 a0 = {0.f, 0.f}, a1 = {0.f, 0.f};
    for (int b = s; b < t; b += 32) {
        int idx = b + lane;
        int c = (idx < t) ? g_adjc[idx] : 0;
        int m = t - b; if (m > 32) m = 32;
        for (int j = 0; j < m; j++) {
            int cc = __shfl_sync(0xffffffffu, c, j);
            size_t co = (size_t)cc * kF + 2 * lane;
            float2 v0 = *(const float2*)(T0 + co);
            float2 v1 = *(const float2*)(T2 + co);
            a0.x += v0.x; a0.y += v0.y;
            a1.x += v1.x; a1.y += v1.y;
        }
    }
    size_t o = (size_t)w * kF + 2 * lane;
    *(float2*)(g_H + 2 * kHS + o) = a0;   // H2
    *(float2*)(g_H + 4 * kHS + o) = a1;   // H4
}

// Pass B, c-side: H3[c]=sum T1[r], H5[c]=sum T3[r]
__global__ void __launch_bounds__(256) k_passB_c() {
    int w = (blockIdx.x * 256 + threadIdx.x) >> 5;
    int lane = threadIdx.x & 31;
    if (w >= kN) return;
    int s = g_colptr[w], t = g_colptr[w + 1];

    const float* T1 = g_H + 7 * kHS;
    const float* T3 = g_H + 9 * kHS;
    float2 a0 = {0.f, 0.f}, a1 = {0.f, 0.f};
    for (int b = s; b < t; b += 32) {
        int idx = b + lane;
        int r = (idx < t) ? g_adjr[idx] : 0;
        int m = t - b; if (m > 32) m = 32;
        for (int j = 0; j < m; j++) {
            int rr = __shfl_sync(0xffffffffu, r, j);
            size_t ro = (size_t)rr * kF + 2 * lane;
            float2 v0 = *(const float2*)(T1 + ro);
            float2 v1 = *(const float2*)(T3 + ro);
            a0.x += v0.x; a0.y += v0.y;
            a1.x += v1.x; a1.y += v1.y;
        }
    }
    size_t o = (size_t)w * kF + 2 * lane;
    *(float2*)(g_H + 3 * kHS + o) = a0;   // H3
    *(float2*)(g_H + 5 * kHS + o) = a1;   // H5
}

// -------------------- fused epilogue GEMM --------------------
//   out[n,:] = sum_i 0.75 * sc_i[n] * (H_i[n,:] @ W_i)  +  0.75 * sum_i b_i
__global__ void __launch_bounds__(128) k_gemm(
    const float* __restrict__ Wsd, const float* __restrict__ bsd,
    const float* __restrict__ Wds, const float* __restrict__ bds,
    const float* __restrict__ W0,  const float* __restrict__ b0,
    const float* __restrict__ W1,  const float* __restrict__ b1,
    const float* __restrict__ W2,  const float* __restrict__ b2,
    const float* __restrict__ W3,  const float* __restrict__ b3,
    float* __restrict__ out, int n) {
    __shared__ float Wsh[64 * 64];
    __shared__ float btot[64];

    int tid  = threadIdx.x;
    int node = blockIdx.x * 128 + tid;

    if (tid < 64)
        btot[tid] = 0.75f * (bsd[tid] + bds[tid] + b0[tid] + b1[tid] + b2[tid] + b3[tid]);

    float acc[64];
#pragma unroll
    for (int f = 0; f < 64; f++) acc[f] = 0.f;

    const float* Ws[6] = {Wsd, Wds, W0, W1, W2, W3};

#pragma unroll 1
    for (int i = 0; i < 6; i++) {
        __syncthreads();
        {
            const float4* src = (const float4*)Ws[i];
            float4* dst = (float4*)Wsh;
#pragma unroll
            for (int j = 0; j < 8; j++) dst[tid + 128 * j] = src[tid + 128 * j];
        }
        __syncthreads();

        if (node < n) {
            float s = 0.75f * g_sc[(size_t)i * kN + node];
            const float* hrow = g_H + (size_t)i * kHS + (size_t)node * kF;
#pragma unroll 1
            for (int k = 0; k < 64; k += 4) {
                float4 h = *(const float4*)(hrow + k);
                float hv0 = h.x * s, hv1 = h.y * s, hv2 = h.z * s, hv3 = h.w * s;
#pragma unroll
                for (int f = 0; f < 64; f++) {
                    acc[f] += hv0 * Wsh[(k + 0) * 64 + f];
                    acc[f] += hv1 * Wsh[(k + 1) * 64 + f];
                    acc[f] += hv2 * Wsh[(k + 2) * 64 + f];
                    acc[f] += hv3 * Wsh[(k + 3) * 64 + f];
                }
            }
        }
    }

    if (node < n) {
#pragma unroll
        for (int f = 0; f < 64; f += 4) {
            float4 o;
            o.x = acc[f + 0] + btot[f + 0];
            o.y = acc[f + 1] + btot[f + 1];
            o.z = acc[f + 2] + btot[f + 2];
            o.w = acc[f + 3] + btot[f + 3];
            *(float4*)(out + (size_t)node * kF + f) = o;
        }
    }
}

// -------------------- launcher --------------------

extern "C" void kernel_launch(void* const* d_in, const int* in_sizes, int n_in,
                              void* d_out, int out_size) {
    const float* x  = (const float*)d_in[0];
    const int*   ei = (const int*)d_in[1];

    int nnodes = in_sizes[0] / kF;
    if (nnodes > kN) nnodes = kN;
    int E = in_sizes[1] / 2;
    if (E > kE) E = kE;

    const int tb = 256;
    int nb = (nnodes + tb - 1) / tb;
    int eb = (E + tb - 1) / tb;

    k_zero_cnt<<<nb, tb>>>();
    k_count<<<eb, tb>>>(ei, E);
    k_scan<<<1, 1024>>>();
    k_scatter<<<eb, tb>>>(ei, E);
    k_deg2_scales<<<nb, tb>>>(nnodes);

    int pb = (kN * 32 + tb - 1) / tb;   // warp per node
    k_passA_r<<<pb, tb>>>(x);
    k_passA_c<<<pb, tb>>>(x);
    k_passB_r<<<pb, tb>>>();
    k_passB_c<<<pb, tb>>>();

    k_gemm<<<(nnodes + 127) / 128, 128>>>(
        (const float*)d_in[2],  (const float*)d_in[3],
        (const float*)d_in[4],  (const float*)d_in[5],
        (const float*)d_in[6],  (const float*)d_in[7],
        (const float*)d_in[8],  (const float*)d_in[9],
        (const float*)d_in[10], (const float*)d_in[11],
        (const float*)d_in[12], (const float*)d_in[13],
        (float*)d_out, nnodes);
}

// round 4
// speedup vs baseline: 1.9582x; 1.0676x over previous
#include <cuda_runtime.h>
#include <cuda_fp16.h>
#include <cstdint>

// Problem constants (fixed by the dataset)
constexpr int    kN  = 100000;           // nodes
constexpr int    kE  = 1600000;          // directed edges
constexpr int    kF  = 64;               // feature dim
constexpr size_t kHS = (size_t)kN * kF;  // one [N,64] buffer, in floats

// H0..H5 : pre-scaled aggregation outputs (fp32), feed the GEMM directly
__device__ float   g_H[6 * kHS];
// x converted to fp16 (half2 per feature pair): [N][32] half2
__device__ __half2 g_xh[(size_t)kN * 32];
// Interleaved fp16 temporaries:
//   g_TP0[node*64 + 2*f2 + {0:T0, 1:T2}]  — gathered over ROW adjacency (pass B_r)
//   g_TP1[node*64 + 2*f2 + {0:T1, 1:T3}]  — gathered over COL adjacency (pass B_c)
__device__ __half2 g_TP0[(size_t)kN * 64];
__device__ __half2 g_TP1[(size_t)kN * 64];
__device__ float   g_sc[6 * (size_t)kN];    // 0.75 * (iso, isi, sAAt, sAtA, sAAo, sAAi)
__device__ float4  g_p0[kN];                // raw (isi, sAtA, sAAi) per source c  (row pass)
__device__ float4  g_p1[kN];                // raw (iso, sAAt, sAAo) per source r  (col pass)
__device__ int     g_cnt_r[kN], g_cnt_c[kN];
__device__ int     g_rowptr[kN + 1], g_colptr[kN + 1];
__device__ int     g_cur_r[kN], g_cur_c[kN];
__device__ int     g_adjc[kE];              // dst (c) of edges grouped by src r
__device__ int     g_adjr[kE];              // src (r) of edges grouped by dst c

struct alignas(8) h2pair { __half2 a, b; };

__device__ __forceinline__ float invs(float d) {
    return d > 0.f ? rsqrtf(d) : 0.f;
}

// packed f32x2 helpers (Blackwell FFMA2 — only reachable via PTX)
__device__ __forceinline__ void ffma2(unsigned long long& d, unsigned long long a,
                                      unsigned long long b) {
    asm("fma.rn.f32x2 %0, %1, %2, %0;" : "+l"(d) : "l"(a), "l"(b));
}
__device__ __forceinline__ unsigned long long pack2(float v) {
    unsigned long long r;
    asm("mov.b64 %0, {%1, %1};" : "=l"(r) : "f"(v));
    return r;
}
__device__ __forceinline__ float2 unpack2(unsigned long long v) {
    float2 r;
    asm("mov.b64 {%0, %1}, %2;" : "=f"(r.x), "=f"(r.y) : "l"(v));
    return r;
}

// -------------------- x -> fp16 --------------------

__global__ void k_xhalf(const float* __restrict__ x) {
    const size_t total = (size_t)kN * 32;  // half2 count
    for (size_t i = (size_t)blockIdx.x * blockDim.x + threadIdx.x; i < total;
         i += (size_t)gridDim.x * blockDim.x) {
        float2 v = *(const float2*)(x + 2 * i);
        g_xh[i] = __float22half2_rn(v);
    }
}

// -------------------- CSR build --------------------

__global__ void k_zero_cnt() {
    int i = blockIdx.x * blockDim.x + threadIdx.x;
    if (i < kN) { g_cnt_r[i] = 0; g_cnt_c[i] = 0; }
}

__global__ void k_count(const int* __restrict__ ei, int E) {
    int e = blockIdx.x * blockDim.x + threadIdx.x;
    if (e >= E) return;
    atomicAdd(&g_cnt_r[ei[e]], 1);
    atomicAdd(&g_cnt_c[ei[E + e]], 1);
}

// single-block exclusive scan of both count arrays (warp-shuffle based)
__global__ void __launch_bounds__(1024) k_scan() {
    __shared__ int wsum[32];
    __shared__ int carry;
    int lane = threadIdx.x & 31, wid = threadIdx.x >> 5;

    for (int a = 0; a < 2; a++) {
        const int* cnt = a ? g_cnt_c : g_cnt_r;
        int* ptr = a ? g_colptr : g_rowptr;
        int* cur = a ? g_cur_c : g_cur_r;
        if (threadIdx.x == 0) carry = 0;
        __syncthreads();
        for (int base = 0; base < kN; base += 1024) {
            int i = base + threadIdx.x;
            int v = (i < kN) ? cnt[i] : 0;
            int incl = v;
#pragma unroll
            for (int off = 1; off < 32; off <<= 1) {
                int t = __shfl_up_sync(0xffffffffu, incl, off);
                if (lane >= off) incl += t;
            }
            if (lane == 31) wsum[wid] = incl;
            __syncthreads();
            if (wid == 0) {
                int sv = wsum[lane];
                int si = sv;
#pragma unroll
                for (int off = 1; off < 32; off <<= 1) {
                    int t = __shfl_up_sync(0xffffffffu, si, off);
                    if (lane >= off) si += t;
                }
                wsum[lane] = si - sv;  // exclusive warp offset
            }
            __syncthreads();
            int excl = incl - v + wsum[wid] + carry;
            if (i < kN) { ptr[i] = excl; cur[i] = excl; }
            __syncthreads();
            if (wid == 31 && lane == 31) carry = excl + v;  // running total
            __syncthreads();
        }
        if (threadIdx.x == 0) ptr[kN] = carry;
        __syncthreads();
    }
}

__global__ void k_scatter(const int* __restrict__ ei, int E) {
    int e = blockIdx.x * blockDim.x + threadIdx.x;
    if (e >= E) return;
    int r = ei[e];
    int c = ei[E + e];
    g_adjc[atomicAdd(&g_cur_r[r], 1)] = c;
    g_adjr[atomicAdd(&g_cur_c[c], 1)] = r;
}

// -------------------- second-order degrees + scales (no atomics) --------------------

__global__ void k_deg2_scales(int n) {
    int i = blockIdx.x * blockDim.x + threadIdx.x;
    if (i >= n) return;

    float dt0 = 0.f, dt2 = 0.f;
    int s = g_rowptr[i], t = g_rowptr[i + 1];
    for (int e = s; e < t; e++) {
        int c = g_adjc[e];
        dt0 += (float)g_cnt_c[c];   // Av(d_in)
        dt2 += (float)g_cnt_r[c];   // Av(d_out)
    }
    float dt1 = 0.f, dt3 = 0.f;
    s = g_colptr[i]; t = g_colptr[i + 1];
    for (int e = s; e < t; e++) {
        int r = g_adjr[e];
        dt1 += (float)g_cnt_r[r];   // Atv(d_out)
        dt3 += (float)g_cnt_c[r];   // Atv(d_in)
    }

    float iso  = invs((float)g_cnt_r[i]);
    float isi  = invs((float)g_cnt_c[i]);
    float sAAt = invs(dt0);
    float sAtA = invs(dt1);
    float sAAo = invs(dt2);
    float sAAi = invs(dt3);

    // output-side scales, premultiplied by the 0.75 aggregation coefficient
    g_sc[0 * (size_t)kN + i] = 0.75f * iso;
    g_sc[1 * (size_t)kN + i] = 0.75f * isi;
    g_sc[2 * (size_t)kN + i] = 0.75f * sAAt;
    g_sc[3 * (size_t)kN + i] = 0.75f * sAtA;
    g_sc[4 * (size_t)kN + i] = 0.75f * sAAo;
    g_sc[5 * (size_t)kN + i] = 0.75f * sAAi;
    // input-side (gather) scales, raw
    g_p0[i] = make_float4(isi, sAtA, sAAi, 0.f);
    g_p1[i] = make_float4(iso, sAAt, sAAo, 0.f);
}

// -------------------- feature passes: warp-per-node gather-reduce --------------------

// Pass A, r-side: H0[r]=0.75*iso[r]*sum isi[c]x[c];  T1[r]=sum sAtA[c]x[c];  T2[r]=sum sAAi[c]x[c]
__global__ void __launch_bounds__(256) k_passA_r() {
    int w = (blockIdx.x * 256 + threadIdx.x) >> 5;
    int lane = threadIdx.x & 31;
    if (w >= kN) return;
    int s = g_rowptr[w], t = g_rowptr[w + 1];

    float2 a0 = {0.f, 0.f}, a1 = {0.f, 0.f}, a2 = {0.f, 0.f};
    for (int b = s; b < t; b += 32) {
        int idx = b + lane;
        int c = (idx < t) ? g_adjc[idx] : 0;
        int m = t - b; if (m > 32) m = 32;
        for (int j = 0; j < m; j++) {
            int cc = __shfl_sync(0xffffffffu, c, j);
            float2 xv = __half22float2(g_xh[(size_t)cc * 32 + lane]);
            float4 sv = g_p0[cc];
            a0.x += sv.x * xv.x; a0.y += sv.x * xv.y;
            a1.x += sv.y * xv.x; a1.y += sv.y * xv.y;
            a2.x += sv.z * xv.x; a2.y += sv.z * xv.y;
        }
    }
    float s0 = g_sc[0 * (size_t)kN + w];
    size_t o = (size_t)w * kF + 2 * lane;
    *(float2*)(g_H + 0 * kHS + o) = make_float2(s0 * a0.x, s0 * a0.y);   // H0 (scaled)
    g_TP1[(size_t)w * 64 + 2 * lane + 0] = __float22half2_rn(a1);        // T1
    g_TP0[(size_t)w * 64 + 2 * lane + 1] = __float22half2_rn(a2);        // T2
}

// Pass A, c-side: H1[c]=0.75*isi[c]*sum iso[r]x[r];  T0[c]=sum sAAt[r]x[r];  T3[c]=sum sAAo[r]x[r]
__global__ void __launch_bounds__(256) k_passA_c() {
    int w = (blockIdx.x * 256 + threadIdx.x) >> 5;
    int lane = threadIdx.x & 31;
    if (w >= kN) return;
    int s = g_colptr[w], t = g_colptr[w + 1];

    float2 a0 = {0.f, 0.f}, a1 = {0.f, 0.f}, a2 = {0.f, 0.f};
    for (int b = s; b < t; b += 32) {
        int idx = b + lane;
        int r = (idx < t) ? g_adjr[idx] : 0;
        int m = t - b; if (m > 32) m = 32;
        for (int j = 0; j < m; j++) {
            int rr = __shfl_sync(0xffffffffu, r, j);
            float2 xv = __half22float2(g_xh[(size_t)rr * 32 + lane]);
            float4 sv = g_p1[rr];
            a0.x += sv.x * xv.x; a0.y += sv.x * xv.y;
            a1.x += sv.y * xv.x; a1.y += sv.y * xv.y;
            a2.x += sv.z * xv.x; a2.y += sv.z * xv.y;
        }
    }
    float s1 = g_sc[1 * (size_t)kN + w];
    size_t o = (size_t)w * kF + 2 * lane;
    *(float2*)(g_H + 1 * kHS + o) = make_float2(s1 * a0.x, s1 * a0.y);   // H1 (scaled)
    g_TP0[(size_t)w * 64 + 2 * lane + 0] = __float22half2_rn(a1);        // T0
    g_TP1[(size_t)w * 64 + 2 * lane + 1] = __float22half2_rn(a2);        // T3
}

// Pass B, r-side: H2[r]=0.75*sAAt[r]*sum T0[c];  H4[r]=0.75*sAAo[r]*sum T2[c]
__global__ void __launch_bounds__(256) k_passB_r() {
    int w = (blockIdx.x * 256 + threadIdx.x) >> 5;
    int lane = threadIdx.x & 31;
    if (w >= kN) return;
    int s = g_rowptr[w], t = g_rowptr[w + 1];

    float2 a0 = {0.f, 0.f}, a1 = {0.f, 0.f};
    for (int b = s; b < t; b += 32) {
        int idx = b + lane;
        int c = (idx < t) ? g_adjc[idx] : 0;
        int m = t - b; if (m > 32) m = 32;
        for (int j = 0; j < m; j++) {
            int cc = __shfl_sync(0xffffffffu, c, j);
            h2pair p = *(const h2pair*)(g_TP0 + (size_t)cc * 64 + 2 * lane);
            float2 v0 = __half22float2(p.a);   // T0
            float2 v1 = __half22float2(p.b);   // T2
            a0.x += v0.x; a0.y += v0.y;
            a1.x += v1.x; a1.y += v1.y;
        }
    }
    float s2 = g_sc[2 * (size_t)kN + w];
    float s4 = g_sc[4 * (size_t)kN + w];
    size_t o = (size_t)w * kF + 2 * lane;
    *(float2*)(g_H + 2 * kHS + o) = make_float2(s2 * a0.x, s2 * a0.y);   // H2
    *(float2*)(g_H + 4 * kHS + o) = make_float2(s4 * a1.x, s4 * a1.y);   // H4
}

// Pass B, c-side: H3[c]=0.75*sAtA[c]*sum T1[r];  H5[c]=0.75*sAAi[c]*sum T3[r]
__global__ void __launch_bounds__(256) k_passB_c() {
    int w = (blockIdx.x * 256 + threadIdx.x) >> 5;
    int lane = threadIdx.x & 31;
    if (w >= kN) return;
    int s = g_colptr[w], t = g_colptr[w + 1];

    float2 a0 = {0.f, 0.f}, a1 = {0.f, 0.f};
    for (int b = s; b < t; b += 32) {
        int idx = b + lane;
        int r = (idx < t) ? g_adjr[idx] : 0;
        int m = t - b; if (m > 32) m = 32;
        for (int j = 0; j < m; j++) {
            int rr = __shfl_sync(0xffffffffu, r, j);
            h2pair p = *(const h2pair*)(g_TP1 + (size_t)rr * 64 + 2 * lane);
            float2 v0 = __half22float2(p.a);   // T1
            float2 v1 = __half22float2(p.b);   // T3
            a0.x += v0.x; a0.y += v0.y;
            a1.x += v1.x; a1.y += v1.y;
        }
    }
    float s3 = g_sc[3 * (size_t)kN + w];
    float s5 = g_sc[5 * (size_t)kN + w];
    size_t o = (size_t)w * kF + 2 * lane;
    *(float2*)(g_H + 3 * kHS + o) = make_float2(s3 * a0.x, s3 * a0.y);   // H3
    *(float2*)(g_H + 5 * kHS + o) = make_float2(s5 * a1.x, s5 * a1.y);   // H5
}

// -------------------- fused epilogue GEMM (packed f32x2) --------------------
//   out[n,:] = sum_i H'_i[n,:] @ W_i  +  0.75 * sum_i b_i      (H' already scaled)
__global__ void __launch_bounds__(128) k_gemm(
    const float* __restrict__ Wsd, const float* __restrict__ bsd,
    const float* __restrict__ Wds, const float* __restrict__ bds,
    const float* __restrict__ W0,  const float* __restrict__ b0,
    const float* __restrict__ W1,  const float* __restrict__ b1,
    const float* __restrict__ W2,  const float* __restrict__ b2,
    const float* __restrict__ W3,  const float* __restrict__ b3,
    float* __restrict__ out, int n) {
    __shared__ float Wsh[64 * 64];
    __shared__ float btot[64];

    int tid  = threadIdx.x;
    int node = blockIdx.x * 128 + tid;

    if (tid < 64)
        btot[tid] = 0.75f * (bsd[tid] + bds[tid] + b0[tid] + b1[tid] + b2[tid] + b3[tid]);

    unsigned long long acc2[32];
#pragma unroll
    for (int f = 0; f < 32; f++) acc2[f] = 0ull;   // packed (0.f, 0.f)

    const float* Ws[6] = {Wsd, Wds, W0, W1, W2, W3};

#pragma unroll 1
    for (int i = 0; i < 6; i++) {
        __syncthreads();
        {
            const float4* src = (const float4*)Ws[i];
            float4* dst = (float4*)Wsh;
#pragma unroll
            for (int j = 0; j < 8; j++) dst[tid + 128 * j] = src[tid + 128 * j];
        }
        __syncthreads();

        if (node < n) {
            const float* hrow = g_H + (size_t)i * kHS + (size_t)node * kF;
#pragma unroll 1
            for (int k = 0; k < 64; k += 4) {
                float4 h = *(const float4*)(hrow + k);
                unsigned long long hv[4];
                hv[0] = pack2(h.x); hv[1] = pack2(h.y);
                hv[2] = pack2(h.z); hv[3] = pack2(h.w);
#pragma unroll
                for (int kk = 0; kk < 4; kk++) {
                    const ulonglong2* wrow = (const ulonglong2*)(Wsh + (k + kk) * 64);
#pragma unroll
                    for (int f = 0; f < 16; f++) {
                        ulonglong2 w2 = wrow[f];
                        ffma2(acc2[2 * f + 0], hv[kk], w2.x);
                        ffma2(acc2[2 * f + 1], hv[kk], w2.y);
                    }
                }
            }
        }
    }

    if (node < n) {
#pragma unroll
        for (int f = 0; f < 32; f += 2) {
            float2 lo = unpack2(acc2[f]);
            float2 hi = unpack2(acc2[f + 1]);
            float4 o;
            o.x = lo.x + btot[2 * f + 0];
            o.y = lo.y + btot[2 * f + 1];
            o.z = hi.x + btot[2 * f + 2];
            o.w = hi.y + btot[2 * f + 3];
            *(float4*)(out + (size_t)node * kF + 2 * f) = o;
        }
    }
}

// -------------------- launcher --------------------

extern "C" void kernel_launch(void* const* d_in, const int* in_sizes, int n_in,
                              void* d_out, int out_size) {
    const float* x  = (const float*)d_in[0];
    const int*   ei = (const int*)d_in[1];

    int nnodes = in_sizes[0] / kF;
    if (nnodes > kN) nnodes = kN;
    int E = in_sizes[1] / 2;
    if (E > kE) E = kE;

    const int tb = 256;
    int nb = (nnodes + tb - 1) / tb;
    int eb = (E + tb - 1) / tb;

    k_xhalf<<<2048, tb>>>(x);
    k_zero_cnt<<<nb, tb>>>();
    k_count<<<eb, tb>>>(ei, E);
    k_scan<<<1, 1024>>>();
    k_scatter<<<eb, tb>>>(ei, E);
    k_deg2_scales<<<nb, tb>>>(nnodes);

    int pb = (kN * 32 + tb - 1) / tb;   // warp per node
    k_passA_r<<<pb, tb>>>();
    k_passA_c<<<pb, tb>>>();
    k_passB_r<<<pb, tb>>>();
    k_passB_c<<<pb, tb>>>();

    k_gemm<<<(nnodes + 127) / 128, 128>>>(
        (const float*)d_in[2],  (const float*)d_in[3],
        (const float*)d_in[4],  (const float*)d_in[5],
        (const float*)d_in[6],  (const float*)d_in[7],
        (const float*)d_in[8],  (const float*)d_in[9],
        (const float*)d_in[10], (const float*)d_in[11],
        (const float*)d_in[12], (const float*)d_in[13],
        (float*)d_out, nnodes);
}

// round 5
// speedup vs baseline: 2.4251x; 1.2385x over previous
#include <cuda_runtime.h>
#include <cuda_fp16.h>
#include <cstdint>

// Problem constants (fixed by the dataset)
constexpr int    kN  = 100000;           // nodes
constexpr int    kE  = 1600000;          // directed edges
constexpr int    kF  = 64;               // feature dim
constexpr size_t kHS = (size_t)kN * kF;  // one [N,64] buffer, in floats
constexpr int    kNT = 2 * kN;           // concatenated count/ptr length
constexpr int    kScanBlocks = (kNT + 1023) / 1024;

// H0..H5 : pre-scaled aggregation outputs (fp32), feed the GEMM directly
__device__ float   g_H[6 * kHS];
// x converted to fp16 (half2 per feature pair): [N][32] half2
__device__ __half2 g_xh[(size_t)kN * 32];
// Interleaved fp16 temporaries:
//   g_TP0[node*64 + 2*f2 + {0:T0, 1:T2}]  — gathered over ROW adjacency (pass B_r)
//   g_TP1[node*64 + 2*f2 + {0:T1, 1:T3}]  — gathered over COL adjacency (pass B_c)
__device__ __half2 g_TP0[(size_t)kN * 64];
__device__ __half2 g_TP1[(size_t)kN * 64];
__device__ float   g_sc[6 * (size_t)kN];    // 0.75 * (iso, isi, sAAt, sAtA, sAAo, sAAi)
__device__ float4  g_p0[kN];                // raw (isi, sAtA, sAAi) per source c  (row pass)
__device__ float4  g_p1[kN];                // raw (iso, sAAt, sAAo) per source r  (col pass)

// Concatenated CSR: [0,kN) = row-side (out-edges), [kN,2kN) = col-side (in-edges)
__device__ int     g_cnt[kNT];
__device__ int     g_ptr[kNT + 1];
__device__ int     g_cur[kNT];
__device__ int     g_adj[2 * kE];   // row section lists c's, col section lists r's
__device__ int     g_bsum[kScanBlocks];
__device__ int     g_boff[kScanBlocks];

struct alignas(8) h2pair { __half2 a, b; };

__device__ __forceinline__ float invs(float d) {
    return d > 0.f ? rsqrtf(d) : 0.f;
}

// packed f32x2 helpers (Blackwell FFMA2 — only reachable via PTX)
__device__ __forceinline__ void ffma2(unsigned long long& d, unsigned long long a,
                                      unsigned long long b) {
    asm("fma.rn.f32x2 %0, %1, %2, %0;" : "+l"(d) : "l"(a), "l"(b));
}
__device__ __forceinline__ unsigned long long pack2(float v) {
    unsigned long long r;
    asm("mov.b64 %0, {%1, %1};" : "=l"(r) : "f"(v));
    return r;
}
__device__ __forceinline__ float2 unpack2(unsigned long long v) {
    float2 r;
    asm("mov.b64 {%0, %1}, %2;" : "=f"(r.x), "=f"(r.y) : "l"(v));
    return r;
}

// -------------------- x -> fp16 --------------------

__global__ void k_xhalf(const float* __restrict__ x) {
    const size_t total = (size_t)kN * 32;  // half2 count
    for (size_t i = (size_t)blockIdx.x * blockDim.x + threadIdx.x; i < total;
         i += (size_t)gridDim.x * blockDim.x) {
        float2 v = *(const float2*)(x + 2 * i);
        g_xh[i] = __float22half2_rn(v);
    }
}

// -------------------- CSR build --------------------

__global__ void k_zero_cnt() {
    int i = blockIdx.x * blockDim.x + threadIdx.x;
    if (i < kNT) g_cnt[i] = 0;
}

__global__ void k_count(const int* __restrict__ ei, int E) {
    int e = blockIdx.x * blockDim.x + threadIdx.x;
    if (e >= E) return;
    atomicAdd(&g_cnt[ei[e]], 1);
    atomicAdd(&g_cnt[kN + ei[E + e]], 1);
}

// ---- two-level parallel exclusive scan over g_cnt[kNT] ----

__device__ __forceinline__ int block_excl_scan_1024(int v, int* wsum) {
    int lane = threadIdx.x & 31, wid = threadIdx.x >> 5;
    int incl = v;
#pragma unroll
    for (int off = 1; off < 32; off <<= 1) {
        int t = __shfl_up_sync(0xffffffffu, incl, off);
        if (lane >= off) incl += t;
    }
    if (lane == 31) wsum[wid] = incl;
    __syncthreads();
    if (wid == 0) {
        int sv = (lane < 32) ? wsum[lane] : 0;
        int si = sv;
#pragma unroll
        for (int off = 1; off < 32; off <<= 1) {
            int t = __shfl_up_sync(0xffffffffu, si, off);
            if (lane >= off) si += t;
        }
        wsum[lane] = si - sv;  // exclusive warp offsets
    }
    __syncthreads();
    return incl - v + wsum[wid];
}

__global__ void __launch_bounds__(1024) k_scan1() {
    __shared__ int wsum[32];
    int i = blockIdx.x * 1024 + threadIdx.x;
    int v = (i < kNT) ? g_cnt[i] : 0;
    int excl = block_excl_scan_1024(v, wsum);
    if (i < kNT) g_ptr[i] = excl;
    if (threadIdx.x == 1023) g_bsum[blockIdx.x] = excl + v;  // block total
}

__global__ void __launch_bounds__(1024) k_scan2() {
    __shared__ int wsum[32];
    int v = (threadIdx.x < kScanBlocks) ? g_bsum[threadIdx.x] : 0;
    int excl = block_excl_scan_1024(v, wsum);
    if (threadIdx.x < kScanBlocks) g_boff[threadIdx.x] = excl;
    if (threadIdx.x == kScanBlocks - 1) g_ptr[kNT] = excl + v;  // grand total (= 2E)
}

__global__ void __launch_bounds__(1024) k_scan3() {
    int i = blockIdx.x * 1024 + threadIdx.x;
    if (i >= kNT) return;
    int p = g_ptr[i] + g_boff[blockIdx.x];
    g_ptr[i] = p;
    g_cur[i] = p;
}

__global__ void k_scatter(const int* __restrict__ ei, int E) {
    int e = blockIdx.x * blockDim.x + threadIdx.x;
    if (e >= E) return;
    int r = ei[e];
    int c = ei[E + e];
    g_adj[atomicAdd(&g_cur[r], 1)] = c;
    g_adj[atomicAdd(&g_cur[kN + c], 1)] = r;
}

// -------------------- second-order degrees + scales (no atomics) --------------------

__global__ void k_deg2_scales(int n) {
    int i = blockIdx.x * blockDim.x + threadIdx.x;
    if (i >= n) return;

    float dt0 = 0.f, dt2 = 0.f;
    int s = g_ptr[i], t = g_ptr[i + 1];
    for (int e = s; e < t; e++) {
        int c = g_adj[e];
        dt0 += (float)g_cnt[kN + c];   // Av(d_in)
        dt2 += (float)g_cnt[c];        // Av(d_out)
    }
    float dt1 = 0.f, dt3 = 0.f;
    s = g_ptr[kN + i]; t = g_ptr[kN + i + 1];
    for (int e = s; e < t; e++) {
        int r = g_adj[e];
        dt1 += (float)g_cnt[r];        // Atv(d_out)
        dt3 += (float)g_cnt[kN + r];   // Atv(d_in)
    }

    float iso  = invs((float)g_cnt[i]);
    float isi  = invs((float)g_cnt[kN + i]);
    float sAAt = invs(dt0);
    float sAtA = invs(dt1);
    float sAAo = invs(dt2);
    float sAAi = invs(dt3);

    // output-side scales, premultiplied by the 0.75 aggregation coefficient
    g_sc[0 * (size_t)kN + i] = 0.75f * iso;
    g_sc[1 * (size_t)kN + i] = 0.75f * isi;
    g_sc[2 * (size_t)kN + i] = 0.75f * sAAt;
    g_sc[3 * (size_t)kN + i] = 0.75f * sAtA;
    g_sc[4 * (size_t)kN + i] = 0.75f * sAAo;
    g_sc[5 * (size_t)kN + i] = 0.75f * sAAi;
    // input-side (gather) scales, raw
    g_p0[i] = make_float4(isi, sAtA, sAAi, 0.f);
    g_p1[i] = make_float4(iso, sAAt, sAAo, 0.f);
}

// -------------------- feature passes: warp-per-node gather-reduce --------------------

// Pass A, r-side: H0[r]=0.75*iso[r]*sum isi[c]x[c];  T1[r]=sum sAtA[c]x[c];  T2[r]=sum sAAi[c]x[c]
__global__ void __launch_bounds__(256) k_passA_r() {
    int w = (blockIdx.x * 256 + threadIdx.x) >> 5;
    int lane = threadIdx.x & 31;
    if (w >= kN) return;
    int s = g_ptr[w], t = g_ptr[w + 1];

    float2 a0 = {0.f, 0.f}, a1 = {0.f, 0.f}, a2 = {0.f, 0.f};
    for (int b = s; b < t; b += 32) {
        int idx = b + lane;
        int c = (idx < t) ? g_adj[idx] : 0;
        int m = t - b; if (m > 32) m = 32;
        for (int j = 0; j < m; j++) {
            int cc = __shfl_sync(0xffffffffu, c, j);
            float2 xv = __half22float2(g_xh[(size_t)cc * 32 + lane]);
            float4 sv = g_p0[cc];
            a0.x += sv.x * xv.x; a0.y += sv.x * xv.y;
            a1.x += sv.y * xv.x; a1.y += sv.y * xv.y;
            a2.x += sv.z * xv.x; a2.y += sv.z * xv.y;
        }
    }
    float s0 = g_sc[0 * (size_t)kN + w];
    size_t o = (size_t)w * kF + 2 * lane;
    *(float2*)(g_H + 0 * kHS + o) = make_float2(s0 * a0.x, s0 * a0.y);   // H0 (scaled)
    g_TP1[(size_t)w * 64 + 2 * lane + 0] = __float22half2_rn(a1);        // T1
    g_TP0[(size_t)w * 64 + 2 * lane + 1] = __float22half2_rn(a2);        // T2
}

// Pass A, c-side: H1[c]=0.75*isi[c]*sum iso[r]x[r];  T0[c]=sum sAAt[r]x[r];  T3[c]=sum sAAo[r]x[r]
__global__ void __launch_bounds__(256) k_passA_c() {
    int w = (blockIdx.x * 256 + threadIdx.x) >> 5;
    int lane = threadIdx.x & 31;
    if (w >= kN) return;
    int s = g_ptr[kN + w], t = g_ptr[kN + w + 1];

    float2 a0 = {0.f, 0.f}, a1 = {0.f, 0.f}, a2 = {0.f, 0.f};
    for (int b = s; b < t; b += 32) {
        int idx = b + lane;
        int r = (idx < t) ? g_adj[idx] : 0;
        int m = t - b; if (m > 32) m = 32;
        for (int j = 0; j < m; j++) {
            int rr = __shfl_sync(0xffffffffu, r, j);
            float2 xv = __half22float2(g_xh[(size_t)rr * 32 + lane]);
            float4 sv = g_p1[rr];
            a0.x += sv.x * xv.x; a0.y += sv.x * xv.y;
            a1.x += sv.y * xv.x; a1.y += sv.y * xv.y;
            a2.x += sv.z * xv.x; a2.y += sv.z * xv.y;
        }
    }
    float s1 = g_sc[1 * (size_t)kN + w];
    size_t o = (size_t)w * kF + 2 * lane;
    *(float2*)(g_H + 1 * kHS + o) = make_float2(s1 * a0.x, s1 * a0.y);   // H1 (scaled)
    g_TP0[(size_t)w * 64 + 2 * lane + 0] = __float22half2_rn(a1);        // T0
    g_TP1[(size_t)w * 64 + 2 * lane + 1] = __float22half2_rn(a2);        // T3
}

// Pass B, r-side: H2[r]=0.75*sAAt[r]*sum T0[c];  H4[r]=0.75*sAAo[r]*sum T2[c]
__global__ void __launch_bounds__(256) k_passB_r() {
    int w = (blockIdx.x * 256 + threadIdx.x) >> 5;
    int lane = threadIdx.x & 31;
    if (w >= kN) return;
    int s = g_ptr[w], t = g_ptr[w + 1];

    float2 a0 = {0.f, 0.f}, a1 = {0.f, 0.f};
    for (int b = s; b < t; b += 32) {
        int idx = b + lane;
        int c = (idx < t) ? g_adj[idx] : 0;
        int m = t - b; if (m > 32) m = 32;
        for (int j = 0; j < m; j++) {
            int cc = __shfl_sync(0xffffffffu, c, j);
            h2pair p = *(const h2pair*)(g_TP0 + (size_t)cc * 64 + 2 * lane);
            float2 v0 = __half22float2(p.a);   // T0
            float2 v1 = __half22float2(p.b);   // T2
            a0.x += v0.x; a0.y += v0.y;
            a1.x += v1.x; a1.y += v1.y;
        }
    }
    float s2 = g_sc[2 * (size_t)kN + w];
    float s4 = g_sc[4 * (size_t)kN + w];
    size_t o = (size_t)w * kF + 2 * lane;
    *(float2*)(g_H + 2 * kHS + o) = make_float2(s2 * a0.x, s2 * a0.y);   // H2
    *(float2*)(g_H + 4 * kHS + o) = make_float2(s4 * a1.x, s4 * a1.y);   // H4
}

// Pass B, c-side: H3[c]=0.75*sAtA[c]*sum T1[r];  H5[c]=0.75*sAAi[c]*sum T3[r]
__global__ void __launch_bounds__(256) k_passB_c() {
    int w = (blockIdx.x * 256 + threadIdx.x) >> 5;
    int lane = threadIdx.x & 31;
    if (w >= kN) return;
    int s = g_ptr[kN + w], t = g_ptr[kN + w + 1];

    float2 a0 = {0.f, 0.f}, a1 = {0.f, 0.f};
    for (int b = s; b < t; b += 32) {
        int idx = b + lane;
        int r = (idx < t) ? g_adj[idx] : 0;
        int m = t - b; if (m > 32) m = 32;
        for (int j = 0; j < m; j++) {
            int rr = __shfl_sync(0xffffffffu, r, j);
            h2pair p = *(const h2pair*)(g_TP1 + (size_t)rr * 64 + 2 * lane);
            float2 v0 = __half22float2(p.a);   // T1
            float2 v1 = __half22float2(p.b);   // T3
            a0.x += v0.x; a0.y += v0.y;
            a1.x += v1.x; a1.y += v1.y;
        }
    }
    float s3 = g_sc[3 * (size_t)kN + w];
    float s5 = g_sc[5 * (size_t)kN + w];
    size_t o = (size_t)w * kF + 2 * lane;
    *(float2*)(g_H + 3 * kHS + o) = make_float2(s3 * a0.x, s3 * a0.y);   // H3
    *(float2*)(g_H + 5 * kHS + o) = make_float2(s5 * a1.x, s5 * a1.y);   // H5
}

// -------------------- fused epilogue GEMM (packed f32x2) --------------------
//   out[n,:] = sum_i H'_i[n,:] @ W_i  +  0.75 * sum_i b_i      (H' already scaled)
__global__ void __launch_bounds__(128) k_gemm(
    const float* __restrict__ Wsd, const float* __restrict__ bsd,
    const float* __restrict__ Wds, const float* __restrict__ bds,
    const float* __restrict__ W0,  const float* __restrict__ b0,
    const float* __restrict__ W1,  const float* __restrict__ b1,
    const float* __restrict__ W2,  const float* __restrict__ b2,
    const float* __restrict__ W3,  const float* __restrict__ b3,
    float* __restrict__ out, int n) {
    __shared__ float Wsh[64 * 64];
    __shared__ float btot[64];

    int tid  = threadIdx.x;
    int node = blockIdx.x * 128 + tid;

    if (tid < 64)
        btot[tid] = 0.75f * (bsd[tid] + bds[tid] + b0[tid] + b1[tid] + b2[tid] + b3[tid]);

    unsigned long long acc2[32];
#pragma unroll
    for (int f = 0; f < 32; f++) acc2[f] = 0ull;   // packed (0.f, 0.f)

    const float* Ws[6] = {Wsd, Wds, W0, W1, W2, W3};

#pragma unroll 1
    for (int i = 0; i < 6; i++) {
        __syncthreads();
        {
            const float4* src = (const float4*)Ws[i];
            float4* dst = (float4*)Wsh;
#pragma unroll
            for (int j = 0; j < 8; j++) dst[tid + 128 * j] = src[tid + 128 * j];
        }
        __syncthreads();

        if (node < n) {
            const float* hrow = g_H + (size_t)i * kHS + (size_t)node * kF;
#pragma unroll 1
            for (int k = 0; k < 64; k += 4) {
                float4 h = *(const float4*)(hrow + k);
                unsigned long long hv[4];
                hv[0] = pack2(h.x); hv[1] = pack2(h.y);
                hv[2] = pack2(h.z); hv[3] = pack2(h.w);
#pragma unroll
                for (int kk = 0; kk < 4; kk++) {
                    const ulonglong2* wrow = (const ulonglong2*)(Wsh + (k + kk) * 64);
#pragma unroll
                    for (int f = 0; f < 16; f++) {
                        ulonglong2 w2 = wrow[f];
                        ffma2(acc2[2 * f + 0], hv[kk], w2.x);
                        ffma2(acc2[2 * f + 1], hv[kk], w2.y);
                    }
                }
            }
        }
    }

    if (node < n) {
#pragma unroll
        for (int f = 0; f < 32; f += 2) {
            float2 lo = unpack2(acc2[f]);
            float2 hi = unpack2(acc2[f + 1]);
            float4 o;
            o.x = lo.x + btot[2 * f + 0];
            o.y = lo.y + btot[2 * f + 1];
            o.z = hi.x + btot[2 * f + 2];
            o.w = hi.y + btot[2 * f + 3];
            *(float4*)(out + (size_t)node * kF + 2 * f) = o;
        }
    }
}

// -------------------- launcher --------------------

extern "C" void kernel_launch(void* const* d_in, const int* in_sizes, int n_in,
                              void* d_out, int out_size) {
    const float* x  = (const float*)d_in[0];
    const int*   ei = (const int*)d_in[1];

    int nnodes = in_sizes[0] / kF;
    if (nnodes > kN) nnodes = kN;
    int E = in_sizes[1] / 2;
    if (E > kE) E = kE;

    const int tb = 256;
    int nb  = (nnodes + tb - 1) / tb;
    int nb2 = (kNT + tb - 1) / tb;
    int eb  = (E + tb - 1) / tb;

    k_xhalf<<<2048, tb>>>(x);
    k_zero_cnt<<<nb2, tb>>>();
    k_count<<<eb, tb>>>(ei, E);
    k_scan1<<<kScanBlocks, 1024>>>();
    k_scan2<<<1, 1024>>>();
    k_scan3<<<kScanBlocks, 1024>>>();
    k_scatter<<<eb, tb>>>(ei, E);
    k_deg2_scales<<<nb, tb>>>(nnodes);

    int pb = (kN * 32 + tb - 1) / tb;   // warp per node
    k_passA_r<<<pb, tb>>>();
    k_passA_c<<<pb, tb>>>();
    k_passB_r<<<pb, tb>>>();
    k_passB_c<<<pb, tb>>>();

    k_gemm<<<(nnodes + 127) / 128, 128>>>(
        (const float*)d_in[2],  (const float*)d_in[3],
        (const float*)d_in[4],  (const float*)d_in[5],
        (const float*)d_in[6],  (const float*)d_in[7],
        (const float*)d_in[8],  (const float*)d_in[9],
        (const float*)d_in[10], (const float*)d_in[11],
        (const float*)d_in[12], (const float*)d_in[13],
        (float*)d_out, nnodes);
}

// round 6
// speedup vs baseline: 2.4413x; 1.0067x over previous
#include <cuda_runtime.h>
#include <cuda_fp16.h>
#include <cstdint>

// Problem constants (fixed by the dataset)
constexpr int    kN  = 100000;           // nodes
constexpr int    kE  = 1600000;          // directed edges
constexpr int    kF  = 64;               // feature dim
constexpr size_t kHS = (size_t)kN * kF;  // one [N,64] buffer, in floats
constexpr int    kNT = 2 * kN;           // concatenated count/ptr length
constexpr int    kScanBlocks = (kNT + 1023) / 1024;

// H0..H5 : pre-scaled aggregation outputs (fp32), feed the GEMM directly
__device__ float   g_H[6 * kHS];
// x converted to fp16 (half2 per feature pair): [N][32] half2
__device__ __half2 g_xh[(size_t)kN * 32];
// Interleaved fp16 temporaries:
//   g_TP0[node*64 + 2*f2 + {0:T0, 1:T2}]  — gathered over ROW adjacency (pass B, r-side)
//   g_TP1[node*64 + 2*f2 + {0:T1, 1:T3}]  — gathered over COL adjacency (pass B, c-side)
__device__ __half2 g_TP0[(size_t)kN * 64];
__device__ __half2 g_TP1[(size_t)kN * 64];
__device__ float   g_sc[6 * (size_t)kN];    // 0.75 * (iso, isi, sAAt, sAtA, sAAo, sAAi)
__device__ float4  g_p0[kN];                // raw (isi, sAtA, sAAi) per source c  (row pass)
__device__ float4  g_p1[kN];                // raw (iso, sAAt, sAAo) per source r  (col pass)

// Concatenated CSR: [0,kN) = row-side (out-edges), [kN,2kN) = col-side (in-edges)
__device__ int     g_cnt[kNT];
__device__ int     g_ptr[kNT + 1];
__device__ int     g_cur[kNT];
__device__ int     g_adj[2 * kE];   // row section lists c's, col section lists r's
__device__ int     g_bsum[kScanBlocks];
__device__ int     g_boff[kScanBlocks];

struct alignas(8) h2pair { __half2 a, b; };

__device__ __forceinline__ float invs(float d) {
    return d > 0.f ? rsqrtf(d) : 0.f;
}

// packed f32x2 helpers (Blackwell FFMA2 — only reachable via PTX)
__device__ __forceinline__ void ffma2(unsigned long long& d, unsigned long long a,
                                      unsigned long long b) {
    asm("fma.rn.f32x2 %0, %1, %2, %0;" : "+l"(d) : "l"(a), "l"(b));
}
__device__ __forceinline__ unsigned long long pack2(float v) {
    unsigned long long r;
    asm("mov.b64 %0, {%1, %1};" : "=l"(r) : "f"(v));
    return r;
}
__device__ __forceinline__ float2 unpack2(unsigned long long v) {
    float2 r;
    asm("mov.b64 {%0, %1}, %2;" : "=f"(r.x), "=f"(r.y) : "l"(v));
    return r;
}

// -------------------- x -> fp16 --------------------

__global__ void k_xhalf(const float* __restrict__ x) {
    const size_t total = (size_t)kN * 32;  // half2 count
    for (size_t i = (size_t)blockIdx.x * blockDim.x + threadIdx.x; i < total;
         i += (size_t)gridDim.x * blockDim.x) {
        float2 v = *(const float2*)(x + 2 * i);
        g_xh[i] = __float22half2_rn(v);
    }
}

// -------------------- CSR build --------------------

__global__ void k_zero_cnt() {
    int i = blockIdx.x * blockDim.x + threadIdx.x;
    if (i < kNT) g_cnt[i] = 0;
}

__global__ void k_count(const int* __restrict__ ei, int E) {
    int e = blockIdx.x * blockDim.x + threadIdx.x;
    if (e >= E) return;
    atomicAdd(&g_cnt[ei[e]], 1);
    atomicAdd(&g_cnt[kN + ei[E + e]], 1);
}

// ---- two-level parallel exclusive scan over g_cnt[kNT] ----

__device__ __forceinline__ int block_excl_scan_1024(int v, int* wsum) {
    int lane = threadIdx.x & 31, wid = threadIdx.x >> 5;
    int incl = v;
#pragma unroll
    for (int off = 1; off < 32; off <<= 1) {
        int t = __shfl_up_sync(0xffffffffu, incl, off);
        if (lane >= off) incl += t;
    }
    if (lane == 31) wsum[wid] = incl;
    __syncthreads();
    if (wid == 0) {
        int sv = (lane < 32) ? wsum[lane] : 0;
        int si = sv;
#pragma unroll
        for (int off = 1; off < 32; off <<= 1) {
            int t = __shfl_up_sync(0xffffffffu, si, off);
            if (lane >= off) si += t;
        }
        wsum[lane] = si - sv;  // exclusive warp offsets
    }
    __syncthreads();
    return incl - v + wsum[wid];
}

__global__ void __launch_bounds__(1024) k_scan1() {
    __shared__ int wsum[32];
    int i = blockIdx.x * 1024 + threadIdx.x;
    int v = (i < kNT) ? g_cnt[i] : 0;
    int excl = block_excl_scan_1024(v, wsum);
    if (i < kNT) g_ptr[i] = excl;
    if (threadIdx.x == 1023) g_bsum[blockIdx.x] = excl + v;  // block total
}

__global__ void __launch_bounds__(1024) k_scan2() {
    __shared__ int wsum[32];
    int v = (threadIdx.x < kScanBlocks) ? g_bsum[threadIdx.x] : 0;
    int excl = block_excl_scan_1024(v, wsum);
    if (threadIdx.x < kScanBlocks) g_boff[threadIdx.x] = excl;
    if (threadIdx.x == kScanBlocks - 1) g_ptr[kNT] = excl + v;  // grand total (= 2E)
}

__global__ void __launch_bounds__(1024) k_scan3() {
    int i = blockIdx.x * 1024 + threadIdx.x;
    if (i >= kNT) return;
    int p = g_ptr[i] + g_boff[blockIdx.x];
    g_ptr[i] = p;
    g_cur[i] = p;
}

__global__ void k_scatter(const int* __restrict__ ei, int E) {
    int e = blockIdx.x * blockDim.x + threadIdx.x;
    if (e >= E) return;
    int r = ei[e];
    int c = ei[E + e];
    g_adj[atomicAdd(&g_cur[r], 1)] = c;
    g_adj[atomicAdd(&g_cur[kN + c], 1)] = r;
}

// -------------------- second-order degrees + scales (warp per node) --------------------

__global__ void __launch_bounds__(256) k_deg2_scales() {
    int w = (blockIdx.x * 256 + threadIdx.x) >> 5;
    int lane = threadIdx.x & 31;
    if (w >= kN) return;

    float dt0 = 0.f, dt2 = 0.f;
    int s = g_ptr[w], t = g_ptr[w + 1];
    for (int i = s + lane; i < t; i += 32) {
        int c = g_adj[i];
        dt0 += (float)g_cnt[kN + c];   // Av(d_in)
        dt2 += (float)g_cnt[c];        // Av(d_out)
    }
    float dt1 = 0.f, dt3 = 0.f;
    s = g_ptr[kN + w]; t = g_ptr[kN + w + 1];
    for (int i = s + lane; i < t; i += 32) {
        int r = g_adj[i];
        dt1 += (float)g_cnt[r];        // Atv(d_out)
        dt3 += (float)g_cnt[kN + r];   // Atv(d_in)
    }
#pragma unroll
    for (int off = 16; off > 0; off >>= 1) {
        dt0 += __shfl_xor_sync(0xffffffffu, dt0, off);
        dt1 += __shfl_xor_sync(0xffffffffu, dt1, off);
        dt2 += __shfl_xor_sync(0xffffffffu, dt2, off);
        dt3 += __shfl_xor_sync(0xffffffffu, dt3, off);
    }
    if (lane == 0) {
        float iso  = invs((float)g_cnt[w]);
        float isi  = invs((float)g_cnt[kN + w]);
        float sAAt = invs(dt0);
        float sAtA = invs(dt1);
        float sAAo = invs(dt2);
        float sAAi = invs(dt3);

        g_sc[0 * (size_t)kN + w] = 0.75f * iso;
        g_sc[1 * (size_t)kN + w] = 0.75f * isi;
        g_sc[2 * (size_t)kN + w] = 0.75f * sAAt;
        g_sc[3 * (size_t)kN + w] = 0.75f * sAtA;
        g_sc[4 * (size_t)kN + w] = 0.75f * sAAo;
        g_sc[5 * (size_t)kN + w] = 0.75f * sAAi;
        g_p0[w] = make_float4(isi, sAtA, sAAi, 0.f);
        g_p1[w] = make_float4(iso, sAAt, sAAo, 0.f);
    }
}

// -------------------- pass A (both sides, warp per node, x4 unrolled) --------------------
// r-side (gw<kN):  H0[r]=0.75*iso[r]*sum isi[c]x[c]; T1[r]=sum sAtA[c]x[c]; T2[r]=sum sAAi[c]x[c]
// c-side (gw>=kN): H1[c]=0.75*isi[c]*sum iso[r]x[r]; T0[c]=sum sAAt[r]x[r]; T3[c]=sum sAAo[r]x[r]
__global__ void __launch_bounds__(256) k_passA() {
    int gw = (blockIdx.x * 256 + threadIdx.x) >> 5;
    int lane = threadIdx.x & 31;
    if (gw >= kNT) return;
    bool rside = gw < kN;
    int w = rside ? gw : gw - kN;
    int s = g_ptr[gw], t = g_ptr[gw + 1];
    const float4* P = rside ? g_p0 : g_p1;

    float2 a0 = {0.f, 0.f}, a1 = {0.f, 0.f}, a2 = {0.f, 0.f};
    for (int b = s; b < t; b += 32) {
        int idx = b + lane;
        int c = (idx < t) ? g_adj[idx] : 0;
        int m = t - b; if (m > 32) m = 32;
        int j = 0;
        for (; j + 4 <= m; j += 4) {
            int c0 = __shfl_sync(0xffffffffu, c, j);
            int c1 = __shfl_sync(0xffffffffu, c, j + 1);
            int c2 = __shfl_sync(0xffffffffu, c, j + 2);
            int c3 = __shfl_sync(0xffffffffu, c, j + 3);
            float2 x0 = __half22float2(g_xh[(size_t)c0 * 32 + lane]);
            float2 x1 = __half22float2(g_xh[(size_t)c1 * 32 + lane]);
            float2 x2 = __half22float2(g_xh[(size_t)c2 * 32 + lane]);
            float2 x3 = __half22float2(g_xh[(size_t)c3 * 32 + lane]);
            float4 s0 = P[c0];
            float4 s1 = P[c1];
            float4 s2 = P[c2];
            float4 s3 = P[c3];
            a0.x += s0.x * x0.x; a0.y += s0.x * x0.y;
            a1.x += s0.y * x0.x; a1.y += s0.y * x0.y;
            a2.x += s0.z * x0.x; a2.y += s0.z * x0.y;
            a0.x += s1.x * x1.x; a0.y += s1.x * x1.y;
            a1.x += s1.y * x1.x; a1.y += s1.y * x1.y;
            a2.x += s1.z * x1.x; a2.y += s1.z * x1.y;
            a0.x += s2.x * x2.x; a0.y += s2.x * x2.y;
            a1.x += s2.y * x2.x; a1.y += s2.y * x2.y;
            a2.x += s2.z * x2.x; a2.y += s2.z * x2.y;
            a0.x += s3.x * x3.x; a0.y += s3.x * x3.y;
            a1.x += s3.y * x3.x; a1.y += s3.y * x3.y;
            a2.x += s3.z * x3.x; a2.y += s3.z * x3.y;
        }
        for (; j < m; j++) {
            int cc = __shfl_sync(0xffffffffu, c, j);
            float2 xv = __half22float2(g_xh[(size_t)cc * 32 + lane]);
            float4 sv = P[cc];
            a0.x += sv.x * xv.x; a0.y += sv.x * xv.y;
            a1.x += sv.y * xv.x; a1.y += sv.y * xv.y;
            a2.x += sv.z * xv.x; a2.y += sv.z * xv.y;
        }
    }

    size_t o = (size_t)w * kF + 2 * lane;
    if (rside) {
        float s0 = g_sc[0 * (size_t)kN + w];
        *(float2*)(g_H + 0 * kHS + o) = make_float2(s0 * a0.x, s0 * a0.y);   // H0 (scaled)
        g_TP1[(size_t)w * 64 + 2 * lane + 0] = __float22half2_rn(a1);        // T1
        g_TP0[(size_t)w * 64 + 2 * lane + 1] = __float22half2_rn(a2);        // T2
    } else {
        float s1 = g_sc[1 * (size_t)kN + w];
        *(float2*)(g_H + 1 * kHS + o) = make_float2(s1 * a0.x, s1 * a0.y);   // H1 (scaled)
        g_TP0[(size_t)w * 64 + 2 * lane + 0] = __float22half2_rn(a1);        // T0
        g_TP1[(size_t)w * 64 + 2 * lane + 1] = __float22half2_rn(a2);        // T3
    }
}

// -------------------- pass B (both sides, warp per node, x4 unrolled) --------------------
// r-side: H2[r]=0.75*sAAt[r]*sum T0[c];  H4[r]=0.75*sAAo[r]*sum T2[c]
// c-side: H3[c]=0.75*sAtA[c]*sum T1[r];  H5[c]=0.75*sAAi[c]*sum T3[r]
__global__ void __launch_bounds__(256) k_passB() {
    int gw = (blockIdx.x * 256 + threadIdx.x) >> 5;
    int lane = threadIdx.x & 31;
    if (gw >= kNT) return;
    bool rside = gw < kN;
    int w = rside ? gw : gw - kN;
    int s = g_ptr[gw], t = g_ptr[gw + 1];
    const h2pair* TP = (const h2pair*)(rside ? g_TP0 : g_TP1);

    float2 a0 = {0.f, 0.f}, a1 = {0.f, 0.f};
    for (int b = s; b < t; b += 32) {
        int idx = b + lane;
        int c = (idx < t) ? g_adj[idx] : 0;
        int m = t - b; if (m > 32) m = 32;
        int j = 0;
        for (; j + 4 <= m; j += 4) {
            int c0 = __shfl_sync(0xffffffffu, c, j);
            int c1 = __shfl_sync(0xffffffffu, c, j + 1);
            int c2 = __shfl_sync(0xffffffffu, c, j + 2);
            int c3 = __shfl_sync(0xffffffffu, c, j + 3);
            h2pair p0 = TP[(size_t)c0 * 32 + lane];
            h2pair p1 = TP[(size_t)c1 * 32 + lane];
            h2pair p2 = TP[(size_t)c2 * 32 + lane];
            h2pair p3 = TP[(size_t)c3 * 32 + lane];
            float2 u;
            u = __half22float2(p0.a); a0.x += u.x; a0.y += u.y;
            u = __half22float2(p0.b); a1.x += u.x; a1.y += u.y;
            u = __half22float2(p1.a); a0.x += u.x; a0.y += u.y;
            u = __half22float2(p1.b); a1.x += u.x; a1.y += u.y;
            u = __half22float2(p2.a); a0.x += u.x; a0.y += u.y;
            u = __half22float2(p2.b); a1.x += u.x; a1.y += u.y;
            u = __half22float2(p3.a); a0.x += u.x; a0.y += u.y;
            u = __half22float2(p3.b); a1.x += u.x; a1.y += u.y;
        }
        for (; j < m; j++) {
            int cc = __shfl_sync(0xffffffffu, c, j);
            h2pair p = TP[(size_t)cc * 32 + lane];
            float2 u;
            u = __half22float2(p.a); a0.x += u.x; a0.y += u.y;
            u = __half22float2(p.b); a1.x += u.x; a1.y += u.y;
        }
    }

    size_t o = (size_t)w * kF + 2 * lane;
    if (rside) {
        float s2 = g_sc[2 * (size_t)kN + w];
        float s4 = g_sc[4 * (size_t)kN + w];
        *(float2*)(g_H + 2 * kHS + o) = make_float2(s2 * a0.x, s2 * a0.y);   // H2
        *(float2*)(g_H + 4 * kHS + o) = make_float2(s4 * a1.x, s4 * a1.y);   // H4
    } else {
        float s3 = g_sc[3 * (size_t)kN + w];
        float s5 = g_sc[5 * (size_t)kN + w];
        *(float2*)(g_H + 3 * kHS + o) = make_float2(s3 * a0.x, s3 * a0.y);   // H3
        *(float2*)(g_H + 5 * kHS + o) = make_float2(s5 * a1.x, s5 * a1.y);   // H5
    }
}

// -------------------- fused epilogue GEMM (packed f32x2) --------------------
//   out[n,:] = sum_i H'_i[n,:] @ W_i  +  0.75 * sum_i b_i      (H' already scaled)
__global__ void __launch_bounds__(128) k_gemm(
    const float* __restrict__ Wsd, const float* __restrict__ bsd,
    const float* __restrict__ Wds, const float* __restrict__ bds,
    const float* __restrict__ W0,  const float* __restrict__ b0,
    const float* __restrict__ W1,  const float* __restrict__ b1,
    const float* __restrict__ W2,  const float* __restrict__ b2,
    const float* __restrict__ W3,  const float* __restrict__ b3,
    float* __restrict__ out, int n) {
    __shared__ float Wsh[64 * 64];
    __shared__ float btot[64];

    int tid  = threadIdx.x;
    int node = blockIdx.x * 128 + tid;

    if (tid < 64)
        btot[tid] = 0.75f * (bsd[tid] + bds[tid] + b0[tid] + b1[tid] + b2[tid] + b3[tid]);

    unsigned long long acc2[32];
#pragma unroll
    for (int f = 0; f < 32; f++) acc2[f] = 0ull;   // packed (0.f, 0.f)

    const float* Ws[6] = {Wsd, Wds, W0, W1, W2, W3};

#pragma unroll 1
    for (int i = 0; i < 6; i++) {
        __syncthreads();
        {
            const float4* src = (const float4*)Ws[i];
            float4* dst = (float4*)Wsh;
#pragma unroll
            for (int j = 0; j < 8; j++) dst[tid + 128 * j] = src[tid + 128 * j];
        }
        __syncthreads();

        if (node < n) {
            const float* hrow = g_H + (size_t)i * kHS + (size_t)node * kF;
#pragma unroll 1
            for (int k = 0; k < 64; k += 4) {
                float4 h = *(const float4*)(hrow + k);
                unsigned long long hv[4];
                hv[0] = pack2(h.x); hv[1] = pack2(h.y);
                hv[2] = pack2(h.z); hv[3] = pack2(h.w);
#pragma unroll
                for (int kk = 0; kk < 4; kk++) {
                    const ulonglong2* wrow = (const ulonglong2*)(Wsh + (k + kk) * 64);
#pragma unroll
                    for (int f = 0; f < 16; f++) {
                        ulonglong2 w2 = wrow[f];
                        ffma2(acc2[2 * f + 0], hv[kk], w2.x);
                        ffma2(acc2[2 * f + 1], hv[kk], w2.y);
                    }
                }
            }
        }
    }

    if (node < n) {
#pragma unroll
        for (int f = 0; f < 32; f += 2) {
            float2 lo = unpack2(acc2[f]);
            float2 hi = unpack2(acc2[f + 1]);
            float4 o;
            o.x = lo.x + btot[2 * f + 0];
            o.y = lo.y + btot[2 * f + 1];
            o.z = hi.x + btot[2 * f + 2];
            o.w = hi.y + btot[2 * f + 3];
            *(float4*)(out + (size_t)node * kF + 2 * f) = o;
        }
    }
}

// -------------------- launcher --------------------

extern "C" void kernel_launch(void* const* d_in, const int* in_sizes, int n_in,
                              void* d_out, int out_size) {
    const float* x  = (const float*)d_in[0];
    const int*   ei = (const int*)d_in[1];

    int nnodes = in_sizes[0] / kF;
    if (nnodes > kN) nnodes = kN;
    int E = in_sizes[1] / 2;
    if (E > kE) E = kE;

    const int tb = 256;
    int nb2 = (kNT + tb - 1) / tb;
    int eb  = (E + tb - 1) / tb;

    k_xhalf<<<2048, tb>>>(x);
    k_zero_cnt<<<nb2, tb>>>();
    k_count<<<eb, tb>>>(ei, E);
    k_scan1<<<kScanBlocks, 1024>>>();
    k_scan2<<<1, 1024>>>();
    k_scan3<<<kScanBlocks, 1024>>>();
    k_scatter<<<eb, tb>>>(ei, E);

    int wb  = (kN * 32 + tb - 1) / tb;    // warp per node
    int wb2 = (kNT * 32 + tb - 1) / tb;   // warp per node, both sides
    k_deg2_scales<<<wb, tb>>>();
    k_passA<<<wb2, tb>>>();
    k_passB<<<wb2, tb>>>();

    k_gemm<<<(nnodes + 127) / 128, 128>>>(
        (const float*)d_in[2],  (const float*)d_in[3],
        (const float*)d_in[4],  (const float*)d_in[5],
        (const float*)d_in[6],  (const float*)d_in[7],
        (const float*)d_in[8],  (const float*)d_in[9],
        (const float*)d_in[10], (const float*)d_in[11],
        (const float*)d_in[12], (const float*)d_in[13],
        (float*)d_out, nnodes);
}